// round 2
// baseline (speedup 1.0000x reference)
#include <cuda_runtime.h>

// Problem constants
#define NPIX   65536      // B*H*W = 4*128*128
#define CCH    128        // channels
#define NQKV   324        // 81 * 4 heads
#define HW     16384      // H*W per image

// ---------------------------------------------------------------------------
// Scratch (device globals; no dynamic allocation allowed)
// ---------------------------------------------------------------------------
__device__ float g_att[(size_t)NPIX * NQKV];        // [g][h*81+p*9+q]   85 MB
__device__ float g_v[(size_t)NPIX * 9 * CCH];       // [g][q][c]        302 MB
__device__ float g_out[(size_t)NPIX * 9 * CCH];     // [g][p][c]        302 MB
__device__ float g_y[(size_t)NPIX * CCH];           // [g][c]          33.5 MB
__device__ float g_wqkvT[CCH * NQKV];               // [k][o]
__device__ float g_wvT[9 * CCH * CCH];              // [p][j][i]
__device__ float g_projT[CCH * CCH];                // [c][o]

// ---------------------------------------------------------------------------
// Weight transposes (k-major so GEMM B loads are coalesced)
// ---------------------------------------------------------------------------
__global__ void prep_kernel(const float* __restrict__ wqkv,
                            const float* __restrict__ wv,
                            const float* __restrict__ wproj) {
    int t = blockIdx.x * blockDim.x + threadIdx.x;
    if (t < NQKV * CCH) {
        int o = t / CCH, k = t % CCH;
        g_wqkvT[k * NQKV + o] = wqkv[t];
    }
    if (t < 9 * CCH * CCH) {
        int p = t >> 14, i = (t >> 7) & 127, j = t & 127;
        g_wvT[(p << 14) + (j << 7) + i] = wv[t];
    }
    if (t < CCH * CCH) {
        int o = t >> 7, c = t & 127;
        g_projT[(c << 7) + o] = wproj[t];
    }
}

// ---------------------------------------------------------------------------
// Generic 128x128x8 register-blocked SGEMM body. K is fixed at 128.
//   C[M, NTOT] = A[M, 128] * B[128, NTOT]
// 256 threads, 8x8 accumulators per thread.
// ---------------------------------------------------------------------------
template <int NTOT>
__device__ __forceinline__ void sgemm_body(const float* __restrict__ A,
                                           const float* __restrict__ B,
                                           float* __restrict__ Cm) {
    __shared__ float As[8][128];
    __shared__ float Bs[8][128];
    const int tid  = threadIdx.x;
    const int tx   = tid & 15;
    const int ty   = tid >> 4;
    const int bm   = blockIdx.y * 128;
    const int bn   = blockIdx.x * 128;
    const int rowA = tid >> 1;
    const int kcol = (tid & 1) * 4;
    const int rowB = tid >> 5;
    const int colB = (tid & 31) * 4;
    const int bcol = bn + colB;

    const float* Aptr = A + (size_t)(bm + rowA) * 128 + kcol;

    float acc[8][8];
#pragma unroll
    for (int i = 0; i < 8; ++i)
#pragma unroll
        for (int j = 0; j < 8; ++j) acc[i][j] = 0.f;

    for (int kt = 0; kt < 128; kt += 8) {
        float4 a4 = *(const float4*)(Aptr + kt);
        float4 b4 = make_float4(0.f, 0.f, 0.f, 0.f);
        if ((NTOT % 128 == 0) || (bcol < NTOT))
            b4 = *(const float4*)(B + (size_t)(kt + rowB) * NTOT + bcol);
        As[kcol + 0][rowA] = a4.x;
        As[kcol + 1][rowA] = a4.y;
        As[kcol + 2][rowA] = a4.z;
        As[kcol + 3][rowA] = a4.w;
        *(float4*)&Bs[rowB][colB] = b4;
        __syncthreads();
#pragma unroll
        for (int kk = 0; kk < 8; ++kk) {
            float a[8], b[8];
            *(float4*)(a)     = *(const float4*)&As[kk][ty * 8];
            *(float4*)(a + 4) = *(const float4*)&As[kk][ty * 8 + 4];
            *(float4*)(b)     = *(const float4*)&Bs[kk][tx * 8];
            *(float4*)(b + 4) = *(const float4*)&Bs[kk][tx * 8 + 4];
#pragma unroll
            for (int i = 0; i < 8; ++i)
#pragma unroll
                for (int j = 0; j < 8; ++j) acc[i][j] += a[i] * b[j];
        }
        __syncthreads();
    }
#pragma unroll
    for (int i = 0; i < 8; ++i) {
        int row = bm + ty * 8 + i;
#pragma unroll
        for (int j0 = 0; j0 < 8; j0 += 4) {
            int col = bn + tx * 8 + j0;
            if ((NTOT % 128 == 0) || (col < NTOT)) {
                float4 v4 = make_float4(acc[i][j0], acc[i][j0 + 1],
                                        acc[i][j0 + 2], acc[i][j0 + 3]);
                *(float4*)&Cm[(size_t)row * NTOT + col] = v4;
            }
        }
    }
}

// att logits: [NPIX,128] x [128,324] -> g_att
__global__ void __launch_bounds__(256) sgemm_att_kernel(const float* __restrict__ x) {
    sgemm_body<NQKV>(x, g_wqkvT, g_att);
}

// final projection: g_y [NPIX,128] x [128,128] -> out
__global__ void __launch_bounds__(256) sgemm_proj_kernel(float* __restrict__ outp) {
    sgemm_body<CCH>(g_y, g_projT, outp);
}

// ---------------------------------------------------------------------------
// v GEMM with spatially shifted A (zero-padded):
// v[g][p][:] = w_v[p] @ x[neighbor(g, p)]    -> one grid.z slice per p
// ---------------------------------------------------------------------------
__global__ void __launch_bounds__(256) sgemm_v_kernel(const float* __restrict__ x) {
    __shared__ float As[8][128];
    __shared__ float Bs[8][128];
    const int p  = blockIdx.z;
    const int di = p / 3 - 1;
    const int dj = p % 3 - 1;
    const int tid  = threadIdx.x;
    const int tx   = tid & 15;
    const int ty   = tid >> 4;
    const int bm   = blockIdx.y * 128;
    const int rowA = tid >> 1;
    const int kcol = (tid & 1) * 4;
    const int rowB = tid >> 5;
    const int colB = (tid & 31) * 4;

    const int g  = bm + rowA;
    const int b  = g >> 14;
    const int n  = g & (HW - 1);
    const int ii = (n >> 7) + di;
    const int jj = (n & 127) + dj;
    const bool valid = ((unsigned)ii < 128u) && ((unsigned)jj < 128u);
    const int srcpix = valid ? ((b << 14) + (ii << 7) + jj) : 0;
    const float* Aptr = x + ((size_t)srcpix << 7) + kcol;
    const float* Bbase = g_wvT + (p << 14);

    float acc[8][8];
#pragma unroll
    for (int i = 0; i < 8; ++i)
#pragma unroll
        for (int j = 0; j < 8; ++j) acc[i][j] = 0.f;

    for (int kt = 0; kt < 128; kt += 8) {
        float4 a4 = make_float4(0.f, 0.f, 0.f, 0.f);
        if (valid) a4 = *(const float4*)(Aptr + kt);
        float4 b4 = *(const float4*)(Bbase + (size_t)(kt + rowB) * 128 + colB);
        As[kcol + 0][rowA] = a4.x;
        As[kcol + 1][rowA] = a4.y;
        As[kcol + 2][rowA] = a4.z;
        As[kcol + 3][rowA] = a4.w;
        *(float4*)&Bs[rowB][colB] = b4;
        __syncthreads();
#pragma unroll
        for (int kk = 0; kk < 8; ++kk) {
            float a[8], bb[8];
            *(float4*)(a)      = *(const float4*)&As[kk][ty * 8];
            *(float4*)(a + 4)  = *(const float4*)&As[kk][ty * 8 + 4];
            *(float4*)(bb)     = *(const float4*)&Bs[kk][tx * 8];
            *(float4*)(bb + 4) = *(const float4*)&Bs[kk][tx * 8 + 4];
#pragma unroll
            for (int i = 0; i < 8; ++i)
#pragma unroll
                for (int j = 0; j < 8; ++j) acc[i][j] += a[i] * bb[j];
        }
        __syncthreads();
    }
#pragma unroll
    for (int i = 0; i < 8; ++i) {
        int row = bm + ty * 8 + i;   // pixel g
#pragma unroll
        for (int j0 = 0; j0 < 8; j0 += 4) {
            int col = tx * 8 + j0;   // output channel
            float4 v4 = make_float4(acc[i][j0], acc[i][j0 + 1],
                                    acc[i][j0 + 2], acc[i][j0 + 3]);
            *(float4*)&g_v[(size_t)row * 1152 + (p << 7) + col] = v4;
        }
    }
}

// ---------------------------------------------------------------------------
// softmax over q: groups of 9 are contiguous in g_att ([g][h][p][q])
// ---------------------------------------------------------------------------
__global__ void softmax_kernel() {
    int idx = blockIdx.x * blockDim.x + threadIdx.x;
    if (idx >= NPIX * 36) return;
    float* pp = g_att + (size_t)idx * 9;
    const float scale = 0.17677669529663687f;  // 32^-0.5
    float v[9], m = -1e30f;
#pragma unroll
    for (int q = 0; q < 9; ++q) { v[q] = pp[q] * scale; m = fmaxf(m, v[q]); }
    float s = 0.f;
#pragma unroll
    for (int q = 0; q < 9; ++q) { v[q] = expf(v[q] - m); s += v[q]; }
    float inv = 1.f / s;
#pragma unroll
    for (int q = 0; q < 9; ++q) pp[q] = v[q] * inv;
}

// ---------------------------------------------------------------------------
// combine: out[g][p][c] = sum_q att[g][h(c)][p][q] * v[g][q][c]
// one block per pixel, thread = channel; att in smem (warp-uniform h -> bcast)
// ---------------------------------------------------------------------------
__global__ void __launch_bounds__(128) combine_kernel() {
    const int g = blockIdx.x;
    const int c = threadIdx.x;
    __shared__ float att_s[NQKV];
    const float* ap = g_att + (size_t)g * NQKV;
    for (int t = c; t < NQKV; t += 128) att_s[t] = ap[t];
    __syncthreads();
    const int h = c >> 5;
    const float* ah = att_s + h * 81;
    const float* vp = g_v + (size_t)g * 1152 + c;
    float acc[9];
#pragma unroll
    for (int p2 = 0; p2 < 9; ++p2) acc[p2] = 0.f;
#pragma unroll
    for (int q = 0; q < 9; ++q) {
        float vq = vp[q << 7];
#pragma unroll
        for (int p2 = 0; p2 < 9; ++p2) acc[p2] += ah[p2 * 9 + q] * vq;
    }
    float* op = g_out + (size_t)g * 1152 + c;
#pragma unroll
    for (int p2 = 0; p2 < 9; ++p2) op[p2 << 7] = acc[p2];
}

// ---------------------------------------------------------------------------
// fold (as a gather): y(i,j,c) = sum_{dr,ds} out[(i+dr, j+ds)][p=(1-dr,1-ds)][c]
// ---------------------------------------------------------------------------
__global__ void fold_kernel() {
    int idx = blockIdx.x * blockDim.x + threadIdx.x;  // over NPIX*128
    int c = idx & 127;
    int g = idx >> 7;
    int b = g >> 14, n = g & (HW - 1);
    int i = n >> 7, j = n & 127;
    float acc = 0.f;
#pragma unroll
    for (int dr = -1; dr <= 1; ++dr) {
#pragma unroll
        for (int ds = -1; ds <= 1; ++ds) {
            int r = i + dr, s = j + ds;
            if ((unsigned)r < 128u && (unsigned)s < 128u) {
                int gp = (b << 14) + (r << 7) + s;
                int p2 = (1 - dr) * 3 + (1 - ds);
                acc += g_out[(size_t)gp * 1152 + (p2 << 7) + c];
            }
        }
    }
    g_y[idx] = acc;
}

// ---------------------------------------------------------------------------
extern "C" void kernel_launch(void* const* d_in, const int* in_sizes, int n_in,
                              void* d_out, int out_size) {
    const float* x     = (const float*)d_in[0];
    const float* wqkv  = (const float*)d_in[1];
    const float* wv    = (const float*)d_in[2];
    const float* wproj = (const float*)d_in[3];
    float* out = (float*)d_out;

    prep_kernel<<<(9 * CCH * CCH + 255) / 256, 256>>>(wqkv, wv, wproj);

    // att logits: grid N tiles = ceil(324/128)=3, M tiles = 65536/128=512
    sgemm_att_kernel<<<dim3(3, 512, 1), 256>>>(x);

    softmax_kernel<<<(NPIX * 36 + 255) / 256, 256>>>();

    // v: 9 shifted GEMMs
    sgemm_v_kernel<<<dim3(1, 512, 9), 256>>>(x);

    combine_kernel<<<NPIX, 128>>>();

    fold_kernel<<<(NPIX * CCH + 255) / 256, 256>>>();

    sgemm_proj_kernel<<<dim3(1, 512, 1), 256>>>(out);
}

// round 4
// speedup vs baseline: 1.6182x; 1.6182x over previous
#include <cuda_runtime.h>
#include <cuda_bf16.h>
#include <cstdint>

// Problem constants
#define NPIX   65536      // B*H*W = 4*128*128
#define CCH    128        // channels
#define NQKV   324        // 81 * 4 heads
#define HW     16384      // H*W per image
#define NV     1152       // 9 * 128 (U width)

// ---------------------------------------------------------------------------
// Scratch (device globals; no dynamic allocation allowed)
// ---------------------------------------------------------------------------
__device__ __nv_bfloat16 g_xh[(size_t)NPIX * CCH];
__device__ __nv_bfloat16 g_xl[(size_t)NPIX * CCH];
__device__ __nv_bfloat16 g_wqkv_h[NQKV * CCH];
__device__ __nv_bfloat16 g_wqkv_l[NQKV * CCH];
__device__ __nv_bfloat16 g_wv_h[NV * CCH];
__device__ __nv_bfloat16 g_wv_l[NV * CCH];
__device__ __nv_bfloat16 g_wpr_h[CCH * CCH];
__device__ __nv_bfloat16 g_wpr_l[CCH * CCH];
__device__ float g_att[(size_t)NPIX * NQKV];     // logits -> softmax probs
__device__ float g_u[(size_t)NPIX * NV];         // U[g][q*128+c]
__device__ float g_out[(size_t)NPIX * NV];       // combine result [g][p][c]
__device__ __nv_bfloat16 g_yh[(size_t)NPIX * CCH];
__device__ __nv_bfloat16 g_yl[(size_t)NPIX * CCH];

// ---------------------------------------------------------------------------
// bf16 split conversions
// ---------------------------------------------------------------------------
__device__ __forceinline__ void split_bf16(float v, __nv_bfloat16& h, __nv_bfloat16& l) {
    h = __float2bfloat16_rn(v);
    l = __float2bfloat16_rn(v - __bfloat162float(h));
}

__global__ void conv_x_kernel(const float* __restrict__ x) {
    int idx = blockIdx.x * blockDim.x + threadIdx.x;
    if (idx >= NPIX * CCH) return;
    split_bf16(x[idx], g_xh[idx], g_xl[idx]);
}

__global__ void conv_w_kernel(const float* __restrict__ wqkv,
                              const float* __restrict__ wv,
                              const float* __restrict__ wproj) {
    int t = blockIdx.x * blockDim.x + threadIdx.x;
    if (t < NQKV * CCH) split_bf16(wqkv[t], g_wqkv_h[t], g_wqkv_l[t]);
    if (t < NV * CCH)   split_bf16(wv[t],   g_wv_h[t],   g_wv_l[t]);   // w_v[q][i][j] flat == [n][k]
    if (t < CCH * CCH)  split_bf16(wproj[t], g_wpr_h[t], g_wpr_l[t]);
}

// ---------------------------------------------------------------------------
// bf16-split tensor-core GEMM: C[M, NTOT] = A[M,128] * B^T  (B stored [n][k])
// Block: 256 threads (8 warps, 2x4), tile 128x128, full K=128 in smem.
// 3 MMAs per (mf,nf,kstep): Ah*Bh + Ah*Bl + Al*Bh.
// ---------------------------------------------------------------------------
#define SPITCH 136       // smem row pitch in halves (16B pad -> conflict-free)
#define SMEM_BYTES (4 * 128 * SPITCH * 2)

#define MMA_BF16(d, a, b0v, b1v)                                              \
    asm volatile("mma.sync.aligned.m16n8k16.row.col.f32.bf16.bf16.f32 "       \
                 "{%0,%1,%2,%3},{%4,%5,%6,%7},{%8,%9},{%0,%1,%2,%3};"         \
                 : "+f"(d[0]), "+f"(d[1]), "+f"(d[2]), "+f"(d[3])             \
                 : "r"(a[0]), "r"(a[1]), "r"(a[2]), "r"(a[3]),                \
                   "r"(b0v), "r"(b1v))

template <int NTOT>
__device__ __forceinline__ void mma_body(const __nv_bfloat16* __restrict__ Ahg,
                                         const __nv_bfloat16* __restrict__ Alg,
                                         const __nv_bfloat16* __restrict__ Bhg,
                                         const __nv_bfloat16* __restrict__ Blg,
                                         float* __restrict__ C) {
    extern __shared__ __nv_bfloat16 sm[];
    __nv_bfloat16* Ah = sm;
    __nv_bfloat16* Al = sm + 128 * SPITCH;
    __nv_bfloat16* Bh = sm + 2 * 128 * SPITCH;
    __nv_bfloat16* Bl = sm + 3 * 128 * SPITCH;

    const int tid = threadIdx.x;
    const int bm = blockIdx.y * 128;
    const int bn = blockIdx.x * 128;

    // one-shot tile load (K=128 entirely resident)
#pragma unroll
    for (int it = 0; it < 8; ++it) {
        int idx = tid + it * 256;          // 0..2047
        int row = idx >> 4;
        int f4  = idx & 15;                // float4 index within row (16 per row)
        *(float4*)(Ah + row * SPITCH + f4 * 8) =
            ((const float4*)(Ahg + (size_t)(bm + row) * 128))[f4];
        *(float4*)(Al + row * SPITCH + f4 * 8) =
            ((const float4*)(Alg + (size_t)(bm + row) * 128))[f4];
        float4 bh4 = make_float4(0.f, 0.f, 0.f, 0.f);
        float4 bl4 = bh4;
        int brow = bn + row;
        if ((NTOT % 128 == 0) || (brow < NTOT)) {
            bh4 = ((const float4*)(Bhg + (size_t)brow * 128))[f4];
            bl4 = ((const float4*)(Blg + (size_t)brow * 128))[f4];
        }
        *(float4*)(Bh + row * SPITCH + f4 * 8) = bh4;
        *(float4*)(Bl + row * SPITCH + f4 * 8) = bl4;
    }
    __syncthreads();

    const int wid = tid >> 5, lane = tid & 31;
    const int wm = wid >> 2;               // 0..1  (64 rows each)
    const int wn = wid & 3;                // 0..3  (32 cols each)
    const int g  = lane >> 2;              // 0..7
    const int tg = lane & 3;               // 0..3

    float acc[4][4][4];
#pragma unroll
    for (int a = 0; a < 4; ++a)
#pragma unroll
        for (int b = 0; b < 4; ++b)
#pragma unroll
            for (int c = 0; c < 4; ++c) acc[a][b][c] = 0.f;

#pragma unroll
    for (int ks = 0; ks < 8; ++ks) {
        const int k0 = ks * 16 + tg * 2;
        uint32_t ah[4][4], al[4][4];
#pragma unroll
        for (int mf = 0; mf < 4; ++mf) {
            int r0 = wm * 64 + mf * 16 + g;
            ah[mf][0] = *(const uint32_t*)(Ah + r0 * SPITCH + k0);
            ah[mf][1] = *(const uint32_t*)(Ah + (r0 + 8) * SPITCH + k0);
            ah[mf][2] = *(const uint32_t*)(Ah + r0 * SPITCH + k0 + 8);
            ah[mf][3] = *(const uint32_t*)(Ah + (r0 + 8) * SPITCH + k0 + 8);
            al[mf][0] = *(const uint32_t*)(Al + r0 * SPITCH + k0);
            al[mf][1] = *(const uint32_t*)(Al + (r0 + 8) * SPITCH + k0);
            al[mf][2] = *(const uint32_t*)(Al + r0 * SPITCH + k0 + 8);
            al[mf][3] = *(const uint32_t*)(Al + (r0 + 8) * SPITCH + k0 + 8);
        }
#pragma unroll
        for (int nf = 0; nf < 4; ++nf) {
            int cb = wn * 32 + nf * 8 + g;
            uint32_t bh0 = *(const uint32_t*)(Bh + cb * SPITCH + k0);
            uint32_t bh1 = *(const uint32_t*)(Bh + cb * SPITCH + k0 + 8);
            uint32_t bl0 = *(const uint32_t*)(Bl + cb * SPITCH + k0);
            uint32_t bl1 = *(const uint32_t*)(Bl + cb * SPITCH + k0 + 8);
#pragma unroll
            for (int mf = 0; mf < 4; ++mf) {
                MMA_BF16(acc[mf][nf], ah[mf], bh0, bh1);
                MMA_BF16(acc[mf][nf], ah[mf], bl0, bl1);
                MMA_BF16(acc[mf][nf], al[mf], bh0, bh1);
            }
        }
    }

#pragma unroll
    for (int mf = 0; mf < 4; ++mf) {
        int row = bm + wm * 64 + mf * 16 + g;
#pragma unroll
        for (int nf = 0; nf < 4; ++nf) {
            int col = bn + wn * 32 + nf * 8 + tg * 2;
            if ((NTOT % 128 == 0) || (col < NTOT)) {
                *(float2*)&C[(size_t)row * NTOT + col] =
                    make_float2(acc[mf][nf][0], acc[mf][nf][1]);
                *(float2*)&C[(size_t)(row + 8) * NTOT + col] =
                    make_float2(acc[mf][nf][2], acc[mf][nf][3]);
            }
        }
    }
}

__global__ void __launch_bounds__(256) mma_att_kernel() {
    mma_body<NQKV>(g_xh, g_xl, g_wqkv_h, g_wqkv_l, g_att);
}
__global__ void __launch_bounds__(256) mma_u_kernel() {
    mma_body<NV>(g_xh, g_xl, g_wv_h, g_wv_l, g_u);
}
__global__ void __launch_bounds__(256) mma_proj_kernel(float* __restrict__ outp) {
    mma_body<CCH>(g_yh, g_yl, g_wpr_h, g_wpr_l, outp);
}

// ---------------------------------------------------------------------------
// softmax over q: contiguous groups of 9 in g_att ([g][h][p][q])
// ---------------------------------------------------------------------------
__global__ void softmax_kernel() {
    int idx = blockIdx.x * blockDim.x + threadIdx.x;
    if (idx >= NPIX * 36) return;
    float* pp = g_att + (size_t)idx * 9;
    const float scale = 0.17677669529663687f;  // 32^-0.5
    float v[9], m = -1e30f;
#pragma unroll
    for (int q = 0; q < 9; ++q) { v[q] = pp[q] * scale; m = fmaxf(m, v[q]); }
    float s = 0.f;
#pragma unroll
    for (int q = 0; q < 9; ++q) { v[q] = expf(v[q] - m); s += v[q]; }
    float inv = 1.f / s;
#pragma unroll
    for (int q = 0; q < 9; ++q) pp[q] = v[q] * inv;
}

// ---------------------------------------------------------------------------
// combine: out[g][p][c] = sum_q att[g][h(c)][p][q] * v[g][q][c]
// where v[g][q][c] = U[g + off(q)][q][c] (zero outside image)
// ---------------------------------------------------------------------------
__global__ void __launch_bounds__(128) combine_kernel() {
    const int g = blockIdx.x;
    const int c = threadIdx.x;
    __shared__ float att_s[NQKV];
    const float* ap = g_att + (size_t)g * NQKV;
    for (int t = c; t < NQKV; t += 128) att_s[t] = ap[t];
    __syncthreads();
    const int b = g >> 14;
    const int n = g & (HW - 1);
    const int i = n >> 7, j = n & 127;
    float v[9];
#pragma unroll
    for (int q = 0; q < 9; ++q) {
        int ii = i + q / 3 - 1;
        int jj = j + q % 3 - 1;
        bool valid = ((unsigned)ii < 128u) && ((unsigned)jj < 128u);
        v[q] = valid ? g_u[(size_t)((b << 14) + (ii << 7) + jj) * NV + (q << 7) + c]
                     : 0.f;
    }
    const int h = c >> 5;
    const float* ah = att_s + h * 81;
    float acc[9];
#pragma unroll
    for (int p2 = 0; p2 < 9; ++p2) acc[p2] = 0.f;
#pragma unroll
    for (int q = 0; q < 9; ++q) {
        float vq = v[q];
#pragma unroll
        for (int p2 = 0; p2 < 9; ++p2) acc[p2] += ah[p2 * 9 + q] * vq;
    }
    float* op = g_out + (size_t)g * NV + c;
#pragma unroll
    for (int p2 = 0; p2 < 9; ++p2) op[p2 << 7] = acc[p2];
}

// ---------------------------------------------------------------------------
// fold (gather): y(i,j,c) = sum_{dr,ds} out[(i+dr, j+ds)][p=(1-dr,1-ds)][c]
// writes y split into bf16 hi/lo for the projection GEMM
// ---------------------------------------------------------------------------
__global__ void fold_kernel() {
    int idx = blockIdx.x * blockDim.x + threadIdx.x;  // over NPIX*128
    int c = idx & 127;
    int g = idx >> 7;
    int b = g >> 14, n = g & (HW - 1);
    int i = n >> 7, j = n & 127;
    float acc = 0.f;
#pragma unroll
    for (int dr = -1; dr <= 1; ++dr) {
#pragma unroll
        for (int ds = -1; ds <= 1; ++ds) {
            int r = i + dr, s = j + ds;
            if ((unsigned)r < 128u && (unsigned)s < 128u) {
                int gp = (b << 14) + (r << 7) + s;
                int p2 = (1 - dr) * 3 + (1 - ds);
                acc += g_out[(size_t)gp * NV + (p2 << 7) + c];
            }
        }
    }
    split_bf16(acc, g_yh[idx], g_yl[idx]);
}

// ---------------------------------------------------------------------------
extern "C" void kernel_launch(void* const* d_in, const int* in_sizes, int n_in,
                              void* d_out, int out_size) {
    const float* x     = (const float*)d_in[0];
    const float* wqkv  = (const float*)d_in[1];
    const float* wv    = (const float*)d_in[2];
    const float* wproj = (const float*)d_in[3];
    float* out = (float*)d_out;

    cudaFuncSetAttribute(mma_att_kernel,  cudaFuncAttributeMaxDynamicSharedMemorySize, SMEM_BYTES);
    cudaFuncSetAttribute(mma_u_kernel,    cudaFuncAttributeMaxDynamicSharedMemorySize, SMEM_BYTES);
    cudaFuncSetAttribute(mma_proj_kernel, cudaFuncAttributeMaxDynamicSharedMemorySize, SMEM_BYTES);

    conv_x_kernel<<<(NPIX * CCH + 255) / 256, 256>>>(x);
    conv_w_kernel<<<(NV * CCH + 255) / 256, 256>>>(wqkv, wv, wproj);

    mma_att_kernel<<<dim3(3, 512), 256, SMEM_BYTES>>>();
    softmax_kernel<<<(NPIX * 36 + 255) / 256, 256>>>();
    mma_u_kernel<<<dim3(9, 512), 256, SMEM_BYTES>>>();
    combine_kernel<<<NPIX, 128>>>();
    fold_kernel<<<(NPIX * CCH + 255) / 256, 256>>>();
    mma_proj_kernel<<<dim3(1, 512), 256, SMEM_BYTES>>>(out);
}

// round 5
// speedup vs baseline: 1.8668x; 1.1536x over previous
#include <cuda_runtime.h>
#include <cuda_bf16.h>
#include <cuda_fp16.h>
#include <cstdint>

// Problem constants
#define NPIX   65536      // B*H*W = 4*128*128
#define CCH    128        // channels
#define NQKV   324        // 81 * 4 heads
#define HW     16384      // H*W per image
#define NV     1152       // 9 * 128
#define SPITCH 136        // smem row pitch (halves)
#define APITCH 328        // att smem row pitch (halves)

#define GEMM_SMEM (4 * 128 * SPITCH * 2)
#define ATT_SMEM  (GEMM_SMEM + 128 * APITCH * 2)

// ---------------------------------------------------------------------------
// Scratch (device globals)
// ---------------------------------------------------------------------------
__device__ __nv_bfloat16 g_xh[(size_t)NPIX * CCH];
__device__ __nv_bfloat16 g_xl[(size_t)NPIX * CCH];
__device__ __nv_bfloat16 g_wqkv_h[NQKV * CCH];
__device__ __nv_bfloat16 g_wqkv_l[NQKV * CCH];
__device__ __nv_bfloat16 g_wv_h[NV * CCH];
__device__ __nv_bfloat16 g_wv_l[NV * CCH];
__device__ __nv_bfloat16 g_wpr_h[CCH * CCH];
__device__ __nv_bfloat16 g_wpr_l[CCH * CCH];
__device__ __half g_attp[(size_t)NPIX * NQKV];   // softmax probs (fp16)  42 MB
__device__ __half g_u16[(size_t)9 * NPIX * CCH]; // U planes [q][g][c]   151 MB
__device__ __half g_out16[(size_t)NPIX * NV];    // combine out [g][p][c]151 MB
__device__ __nv_bfloat16 g_yh[(size_t)NPIX * CCH];
__device__ __nv_bfloat16 g_yl[(size_t)NPIX * CCH];

// ---------------------------------------------------------------------------
__device__ __forceinline__ void split_bf16(float v, __nv_bfloat16& h, __nv_bfloat16& l) {
    h = __float2bfloat16_rn(v);
    l = __float2bfloat16_rn(v - __bfloat162float(h));
}

__global__ void conv_x_kernel(const float* __restrict__ x) {
    int idx = blockIdx.x * blockDim.x + threadIdx.x;
    if (idx >= NPIX * CCH) return;
    split_bf16(x[idx], g_xh[idx], g_xl[idx]);
}

__global__ void conv_w_kernel(const float* __restrict__ wqkv,
                              const float* __restrict__ wv,
                              const float* __restrict__ wproj) {
    int t = blockIdx.x * blockDim.x + threadIdx.x;
    if (t < NQKV * CCH) split_bf16(wqkv[t], g_wqkv_h[t], g_wqkv_l[t]);
    if (t < NV * CCH)   split_bf16(wv[t],   g_wv_h[t],   g_wv_l[t]);
    if (t < CCH * CCH)  split_bf16(wproj[t], g_wpr_h[t], g_wpr_l[t]);
}

// ---------------------------------------------------------------------------
#define MMA_BF16(d, a, b0v, b1v)                                              \
    asm volatile("mma.sync.aligned.m16n8k16.row.col.f32.bf16.bf16.f32 "       \
                 "{%0,%1,%2,%3},{%4,%5,%6,%7},{%8,%9},{%0,%1,%2,%3};"         \
                 : "+f"(d[0]), "+f"(d[1]), "+f"(d[2]), "+f"(d[3])             \
                 : "r"(a[0]), "r"(a[1]), "r"(a[2]), "r"(a[3]),                \
                   "r"(b0v), "r"(b1v))

// load 128x128 bf16 tile pair (hi/lo) into smem
__device__ __forceinline__ void load_tile(const __nv_bfloat16* __restrict__ Hg,
                                          const __nv_bfloat16* __restrict__ Lg,
                                          __nv_bfloat16* Hs, __nv_bfloat16* Ls,
                                          int base_row, int row_limit, int tid) {
#pragma unroll
    for (int it = 0; it < 8; ++it) {
        int idx = tid + it * 256;
        int row = idx >> 4, f4 = idx & 15;
        int grow = base_row + row;
        float4 h4 = make_float4(0.f, 0.f, 0.f, 0.f), l4 = h4;
        if (grow < row_limit) {
            h4 = ((const float4*)(Hg + (size_t)grow * 128))[f4];
            l4 = ((const float4*)(Lg + (size_t)grow * 128))[f4];
        }
        *(float4*)(Hs + row * SPITCH + f4 * 8) = h4;
        *(float4*)(Ls + row * SPITCH + f4 * 8) = l4;
    }
}

// 8-kstep MMA over resident smem tiles; acc[4][4][4]
__device__ __forceinline__ void mma_compute(const __nv_bfloat16* Ah, const __nv_bfloat16* Al,
                                            const __nv_bfloat16* Bh, const __nv_bfloat16* Bl,
                                            int wm, int wn, int g, int tg,
                                            float acc[4][4][4]) {
#pragma unroll
    for (int a = 0; a < 4; ++a)
#pragma unroll
        for (int b = 0; b < 4; ++b)
#pragma unroll
            for (int c = 0; c < 4; ++c) acc[a][b][c] = 0.f;
#pragma unroll
    for (int ks = 0; ks < 8; ++ks) {
        const int k0 = ks * 16 + tg * 2;
        uint32_t ah[4][4], al[4][4];
#pragma unroll
        for (int mf = 0; mf < 4; ++mf) {
            int r0 = wm * 64 + mf * 16 + g;
            ah[mf][0] = *(const uint32_t*)(Ah + r0 * SPITCH + k0);
            ah[mf][1] = *(const uint32_t*)(Ah + (r0 + 8) * SPITCH + k0);
            ah[mf][2] = *(const uint32_t*)(Ah + r0 * SPITCH + k0 + 8);
            ah[mf][3] = *(const uint32_t*)(Ah + (r0 + 8) * SPITCH + k0 + 8);
            al[mf][0] = *(const uint32_t*)(Al + r0 * SPITCH + k0);
            al[mf][1] = *(const uint32_t*)(Al + (r0 + 8) * SPITCH + k0);
            al[mf][2] = *(const uint32_t*)(Al + r0 * SPITCH + k0 + 8);
            al[mf][3] = *(const uint32_t*)(Al + (r0 + 8) * SPITCH + k0 + 8);
        }
#pragma unroll
        for (int nf = 0; nf < 4; ++nf) {
            int cb = wn * 32 + nf * 8 + g;
            uint32_t bh0 = *(const uint32_t*)(Bh + cb * SPITCH + k0);
            uint32_t bh1 = *(const uint32_t*)(Bh + cb * SPITCH + k0 + 8);
            uint32_t bl0 = *(const uint32_t*)(Bl + cb * SPITCH + k0);
            uint32_t bl1 = *(const uint32_t*)(Bl + cb * SPITCH + k0 + 8);
#pragma unroll
            for (int mf = 0; mf < 4; ++mf) {
                MMA_BF16(acc[mf][nf], ah[mf], bh0, bh1);
                MMA_BF16(acc[mf][nf], ah[mf], bl0, bl1);
                MMA_BF16(acc[mf][nf], al[mf], bh0, bh1);
            }
        }
    }
}

// ---------------------------------------------------------------------------
// att GEMM (all 3 n-tiles, A resident) + in-smem softmax + fp16 prob store
// ---------------------------------------------------------------------------
__global__ void __launch_bounds__(256) att_kernel() {
    extern __shared__ __nv_bfloat16 sm[];
    __nv_bfloat16* Ah = sm;
    __nv_bfloat16* Al = sm + 128 * SPITCH;
    __nv_bfloat16* Bh = sm + 2 * 128 * SPITCH;
    __nv_bfloat16* Bl = sm + 3 * 128 * SPITCH;
    __half* att_s = (__half*)(sm + 4 * 128 * SPITCH);

    const int tid = threadIdx.x;
    const int bm = blockIdx.x * 128;
    const int wid = tid >> 5, lane = tid & 31;
    const int wm = wid >> 2, wn = wid & 3;
    const int g = lane >> 2, tg = lane & 3;

    load_tile(g_xh, g_xl, Ah, Al, bm, NPIX, tid);

    for (int nt = 0; nt < 3; ++nt) {
        __syncthreads();
        load_tile(g_wqkv_h, g_wqkv_l, Bh, Bl, nt * 128, NQKV, tid);
        __syncthreads();
        float acc[4][4][4];
        mma_compute(Ah, Al, Bh, Bl, wm, wn, g, tg, acc);
#pragma unroll
        for (int mf = 0; mf < 4; ++mf) {
            int row = wm * 64 + mf * 16 + g;
#pragma unroll
            for (int nf = 0; nf < 4; ++nf) {
                int cc = nt * 128 + wn * 32 + nf * 8 + tg * 2;
                if (cc < NQKV) {
                    *(half2*)(att_s + row * APITCH + cc) =
                        __floats2half2_rn(acc[mf][nf][0], acc[mf][nf][1]);
                    *(half2*)(att_s + (row + 8) * APITCH + cc) =
                        __floats2half2_rn(acc[mf][nf][2], acc[mf][nf][3]);
                }
            }
        }
    }
    __syncthreads();

    // softmax over each 9-group, in smem
    const float scale = 0.17677669529663687f;  // 32^-0.5
    for (int t = tid; t < 128 * 36; t += 256) {
        int row = t / 36, grp = t % 36;
        __half* pp = att_s + row * APITCH + grp * 9;
        float v[9], m = -1e30f;
#pragma unroll
        for (int q = 0; q < 9; ++q) { v[q] = __half2float(pp[q]) * scale; m = fmaxf(m, v[q]); }
        float s = 0.f;
#pragma unroll
        for (int q = 0; q < 9; ++q) { v[q] = __expf(v[q] - m); s += v[q]; }
        float inv = 1.f / s;
#pragma unroll
        for (int q = 0; q < 9; ++q) pp[q] = __float2half_rn(v[q] * inv);
    }
    __syncthreads();

    // coalesced prob store
    for (int t = tid; t < 128 * NQKV; t += 256) {
        int row = t / NQKV, col = t - row * NQKV;
        g_attp[(size_t)(bm + row) * NQKV + col] = att_s[row * APITCH + col];
    }
}

// ---------------------------------------------------------------------------
// U GEMM: all 9 q-tiles with A resident; fp16 out to planes [q][g][c]
// ---------------------------------------------------------------------------
__global__ void __launch_bounds__(256) mma_u_kernel() {
    extern __shared__ __nv_bfloat16 sm[];
    __nv_bfloat16* Ah = sm;
    __nv_bfloat16* Al = sm + 128 * SPITCH;
    __nv_bfloat16* Bh = sm + 2 * 128 * SPITCH;
    __nv_bfloat16* Bl = sm + 3 * 128 * SPITCH;

    const int tid = threadIdx.x;
    const int bm = blockIdx.x * 128;
    const int wid = tid >> 5, lane = tid & 31;
    const int wm = wid >> 2, wn = wid & 3;
    const int g = lane >> 2, tg = lane & 3;

    load_tile(g_xh, g_xl, Ah, Al, bm, NPIX, tid);

    for (int q = 0; q < 9; ++q) {
        __syncthreads();
        load_tile(g_wv_h, g_wv_l, Bh, Bl, q * 128, NV, tid);
        __syncthreads();
        float acc[4][4][4];
        mma_compute(Ah, Al, Bh, Bl, wm, wn, g, tg, acc);
        __half* plane = g_u16 + (size_t)q * NPIX * CCH;
#pragma unroll
        for (int mf = 0; mf < 4; ++mf) {
            int row = bm + wm * 64 + mf * 16 + g;
#pragma unroll
            for (int nf = 0; nf < 4; ++nf) {
                int col = wn * 32 + nf * 8 + tg * 2;
                *(half2*)(plane + (size_t)row * 128 + col) =
                    __floats2half2_rn(acc[mf][nf][0], acc[mf][nf][1]);
                *(half2*)(plane + (size_t)(row + 8) * 128 + col) =
                    __floats2half2_rn(acc[mf][nf][2], acc[mf][nf][3]);
            }
        }
    }
}

// ---------------------------------------------------------------------------
// projection GEMM: y (bf16 split) x wproj -> fp32 out
// ---------------------------------------------------------------------------
__global__ void __launch_bounds__(256) mma_proj_kernel(float* __restrict__ outp) {
    extern __shared__ __nv_bfloat16 sm[];
    __nv_bfloat16* Ah = sm;
    __nv_bfloat16* Al = sm + 128 * SPITCH;
    __nv_bfloat16* Bh = sm + 2 * 128 * SPITCH;
    __nv_bfloat16* Bl = sm + 3 * 128 * SPITCH;

    const int tid = threadIdx.x;
    const int bm = blockIdx.x * 128;
    const int wid = tid >> 5, lane = tid & 31;
    const int wm = wid >> 2, wn = wid & 3;
    const int g = lane >> 2, tg = lane & 3;

    load_tile(g_yh, g_yl, Ah, Al, bm, NPIX, tid);
    load_tile(g_wpr_h, g_wpr_l, Bh, Bl, 0, CCH, tid);
    __syncthreads();
    float acc[4][4][4];
    mma_compute(Ah, Al, Bh, Bl, wm, wn, g, tg, acc);
#pragma unroll
    for (int mf = 0; mf < 4; ++mf) {
        int row = bm + wm * 64 + mf * 16 + g;
#pragma unroll
        for (int nf = 0; nf < 4; ++nf) {
            int col = wn * 32 + nf * 8 + tg * 2;
            *(float2*)&outp[(size_t)row * 128 + col] =
                make_float2(acc[mf][nf][0], acc[mf][nf][1]);
            *(float2*)&outp[(size_t)(row + 8) * 128 + col] =
                make_float2(acc[mf][nf][2], acc[mf][nf][3]);
        }
    }
}

// ---------------------------------------------------------------------------
// combine: out[g][p][c] = sum_q att[g][h(c)][p][q] * U[g+off(q)][q][c]
// 2 pixels per block (256 threads)
// ---------------------------------------------------------------------------
__global__ void __launch_bounds__(256) combine_kernel() {
    const int sub = threadIdx.x >> 7;        // 0..1
    const int c   = threadIdx.x & 127;
    const int g   = blockIdx.x * 2 + sub;
    __shared__ float att_s[2][NQKV];
    const __half* ap = g_attp + (size_t)g * NQKV;
    for (int t = c; t < NQKV; t += 128) att_s[sub][t] = __half2float(ap[t]);
    __syncthreads();

    const int b = g >> 14;
    const int n = g & (HW - 1);
    const int i = n >> 7, j = n & 127;
    float v[9];
#pragma unroll
    for (int q = 0; q < 9; ++q) {
        int ii = i + q / 3 - 1;
        int jj = j + q % 3 - 1;
        bool valid = ((unsigned)ii < 128u) && ((unsigned)jj < 128u);
        v[q] = valid ? __half2float(
                   g_u16[((size_t)q * NPIX + ((b << 14) + (ii << 7) + jj)) * 128 + c])
                     : 0.f;
    }
    const float* ah = att_s[sub] + (c >> 5) * 81;
    float acc[9];
#pragma unroll
    for (int p2 = 0; p2 < 9; ++p2) acc[p2] = 0.f;
#pragma unroll
    for (int q = 0; q < 9; ++q) {
        float vq = v[q];
#pragma unroll
        for (int p2 = 0; p2 < 9; ++p2) acc[p2] += ah[p2 * 9 + q] * vq;
    }
    __half* op = g_out16 + (size_t)g * NV + c;
#pragma unroll
    for (int p2 = 0; p2 < 9; ++p2) op[p2 << 7] = __float2half_rn(acc[p2]);
}

// ---------------------------------------------------------------------------
// fold (gather), half2-vectorized; writes bf16 hi/lo y
// ---------------------------------------------------------------------------
__global__ void fold_kernel() {
    int idx = blockIdx.x * blockDim.x + threadIdx.x;  // over NPIX*64
    if (idx >= NPIX * 64) return;
    int c2 = idx & 63;
    int g = idx >> 6;
    int b = g >> 14, n = g & (HW - 1);
    int i = n >> 7, j = n & 127;
    float ax = 0.f, ay = 0.f;
#pragma unroll
    for (int dr = -1; dr <= 1; ++dr) {
#pragma unroll
        for (int ds = -1; ds <= 1; ++ds) {
            int r = i + dr, s = j + ds;
            if ((unsigned)r < 128u && (unsigned)s < 128u) {
                int gp = (b << 14) + (r << 7) + s;
                int p2 = (1 - dr) * 3 + (1 - ds);
                half2 h = *(const half2*)&g_out16[(size_t)gp * NV + (p2 << 7) + c2 * 2];
                float2 f = __half22float2(h);
                ax += f.x; ay += f.y;
            }
        }
    }
    __nv_bfloat16 hx, lx, hy, ly;
    split_bf16(ax, hx, lx);
    split_bf16(ay, hy, ly);
    size_t o = (size_t)g * 128 + c2 * 2;
    *(__nv_bfloat162*)&g_yh[o] = __nv_bfloat162(hx, hy);
    *(__nv_bfloat162*)&g_yl[o] = __nv_bfloat162(lx, ly);
}

// ---------------------------------------------------------------------------
extern "C" void kernel_launch(void* const* d_in, const int* in_sizes, int n_in,
                              void* d_out, int out_size) {
    const float* x     = (const float*)d_in[0];
    const float* wqkv  = (const float*)d_in[1];
    const float* wv    = (const float*)d_in[2];
    const float* wproj = (const float*)d_in[3];
    float* out = (float*)d_out;

    cudaFuncSetAttribute(att_kernel,      cudaFuncAttributeMaxDynamicSharedMemorySize, ATT_SMEM);
    cudaFuncSetAttribute(mma_u_kernel,    cudaFuncAttributeMaxDynamicSharedMemorySize, GEMM_SMEM);
    cudaFuncSetAttribute(mma_proj_kernel, cudaFuncAttributeMaxDynamicSharedMemorySize, GEMM_SMEM);

    conv_x_kernel<<<(NPIX * CCH + 255) / 256, 256>>>(x);
    conv_w_kernel<<<(NV * CCH + 255) / 256, 256>>>(wqkv, wv, wproj);

    att_kernel<<<512, 256, ATT_SMEM>>>();
    mma_u_kernel<<<512, 256, GEMM_SMEM>>>();
    combine_kernel<<<NPIX / 2, 256>>>();
    fold_kernel<<<(NPIX * 64 + 255) / 256, 256>>>();
    mma_proj_kernel<<<512, 256, GEMM_SMEM>>>(out);
}

// round 6
// speedup vs baseline: 2.1336x; 1.1429x over previous
#include <cuda_runtime.h>
#include <cuda_bf16.h>
#include <cuda_fp16.h>
#include <cstdint>

// Problem constants
#define NPIX   65536      // B*H*W = 4*128*128
#define CCH    128        // channels
#define NQKV   324        // 81 * 4 heads
#define HW     16384      // H*W per image
#define NV     1152       // 9 * 128
#define SPITCH 136        // smem row pitch (halves)
#define APITCH 328        // att smem row pitch (halves)
#define TILE_H (128 * SPITCH)            // halves per tile buffer

#define GEMM_SMEM (4 * TILE_H * 2)                 // A(h,l) + B(h,l)
#define U_SMEM    (6 * TILE_H * 2)                 // A(h,l) + 2x B(h,l)
#define ATT_SMEM  (GEMM_SMEM + 128 * APITCH * 2)

// ---------------------------------------------------------------------------
// Scratch (device globals)
// ---------------------------------------------------------------------------
__device__ __nv_bfloat16 g_xh[(size_t)NPIX * CCH];
__device__ __nv_bfloat16 g_xl[(size_t)NPIX * CCH];
__device__ __nv_bfloat16 g_wqkv_h[NQKV * CCH];
__device__ __nv_bfloat16 g_wqkv_l[NQKV * CCH];
__device__ __nv_bfloat16 g_wv_h[NV * CCH];
__device__ __nv_bfloat16 g_wv_l[NV * CCH];
__device__ __nv_bfloat16 g_wpr_h[CCH * CCH];
__device__ __nv_bfloat16 g_wpr_l[CCH * CCH];
__device__ __half g_attp[(size_t)NPIX * NQKV];   // softmax probs (fp16)
__device__ __half g_u16[(size_t)9 * NPIX * CCH]; // U planes [q][g][c]
__device__ __half g_out16[(size_t)NPIX * NV];    // combine out [g][p][c]
__device__ __nv_bfloat16 g_yh[(size_t)NPIX * CCH];
__device__ __nv_bfloat16 g_yl[(size_t)NPIX * CCH];

// ---------------------------------------------------------------------------
__device__ __forceinline__ void split_bf16(float v, __nv_bfloat16& h, __nv_bfloat16& l) {
    h = __float2bfloat16_rn(v);
    l = __float2bfloat16_rn(v - __bfloat162float(h));
}

__global__ void conv_x_kernel(const float* __restrict__ x) {
    int idx = blockIdx.x * blockDim.x + threadIdx.x;   // over NPIX*64
    if (idx >= NPIX * 64) return;
    float2 f = ((const float2*)x)[idx];
    __nv_bfloat16 hx, lx, hy, ly;
    split_bf16(f.x, hx, lx);
    split_bf16(f.y, hy, ly);
    ((__nv_bfloat162*)g_xh)[idx] = __nv_bfloat162(hx, hy);
    ((__nv_bfloat162*)g_xl)[idx] = __nv_bfloat162(lx, ly);
}

__global__ void conv_w_kernel(const float* __restrict__ wqkv,
                              const float* __restrict__ wv,
                              const float* __restrict__ wproj) {
    int t = blockIdx.x * blockDim.x + threadIdx.x;
    if (t < NQKV * CCH) split_bf16(wqkv[t], g_wqkv_h[t], g_wqkv_l[t]);
    if (t < NV * CCH)   split_bf16(wv[t],   g_wv_h[t],   g_wv_l[t]);
    if (t < CCH * CCH)  split_bf16(wproj[t], g_wpr_h[t], g_wpr_l[t]);
}

// ---------------------------------------------------------------------------
#define MMA_BF16(d, a, b0v, b1v)                                              \
    asm volatile("mma.sync.aligned.m16n8k16.row.col.f32.bf16.bf16.f32 "       \
                 "{%0,%1,%2,%3},{%4,%5,%6,%7},{%8,%9},{%0,%1,%2,%3};"         \
                 : "+f"(d[0]), "+f"(d[1]), "+f"(d[2]), "+f"(d[3])             \
                 : "r"(a[0]), "r"(a[1]), "r"(a[2]), "r"(a[3]),                \
                   "r"(b0v), "r"(b1v))

__device__ __forceinline__ void cp_async16(void* sptr, const void* gptr) {
    uint32_t saddr = (uint32_t)__cvta_generic_to_shared(sptr);
    asm volatile("cp.async.cg.shared.global [%0], [%1], 16;" :: "r"(saddr), "l"(gptr));
}
#define CP_COMMIT()  asm volatile("cp.async.commit_group;")
#define CP_WAIT(n)   asm volatile("cp.async.wait_group %0;" :: "n"(n))

// synchronous tile pair load (bounds-checked) for att/proj
__device__ __forceinline__ void load_tile(const __nv_bfloat16* __restrict__ Hg,
                                          const __nv_bfloat16* __restrict__ Lg,
                                          __nv_bfloat16* Hs, __nv_bfloat16* Ls,
                                          int base_row, int row_limit, int tid) {
#pragma unroll
    for (int it = 0; it < 8; ++it) {
        int idx = tid + it * 256;
        int row = idx >> 4, f4 = idx & 15;
        int grow = base_row + row;
        float4 h4 = make_float4(0.f, 0.f, 0.f, 0.f), l4 = h4;
        if (grow < row_limit) {
            h4 = ((const float4*)(Hg + (size_t)grow * 128))[f4];
            l4 = ((const float4*)(Lg + (size_t)grow * 128))[f4];
        }
        *(float4*)(Hs + row * SPITCH + f4 * 8) = h4;
        *(float4*)(Ls + row * SPITCH + f4 * 8) = l4;
    }
}

// async tile pair load (no bounds: rows guaranteed in range)
__device__ __forceinline__ void load_tile_async(const __nv_bfloat16* __restrict__ Hg,
                                                const __nv_bfloat16* __restrict__ Lg,
                                                __nv_bfloat16* Hs, __nv_bfloat16* Ls,
                                                int base_row, int tid) {
#pragma unroll
    for (int it = 0; it < 8; ++it) {
        int idx = tid + it * 256;
        int row = idx >> 4, f4 = idx & 15;
        cp_async16(Hs + row * SPITCH + f4 * 8, Hg + (size_t)(base_row + row) * 128 + f4 * 8);
        cp_async16(Ls + row * SPITCH + f4 * 8, Lg + (size_t)(base_row + row) * 128 + f4 * 8);
    }
}

// 8-kstep MMA over resident smem tiles; acc[4][4][4]
__device__ __forceinline__ void mma_compute(const __nv_bfloat16* Ah, const __nv_bfloat16* Al,
                                            const __nv_bfloat16* Bh, const __nv_bfloat16* Bl,
                                            int wm, int wn, int g, int tg,
                                            float acc[4][4][4]) {
#pragma unroll
    for (int a = 0; a < 4; ++a)
#pragma unroll
        for (int b = 0; b < 4; ++b)
#pragma unroll
            for (int c = 0; c < 4; ++c) acc[a][b][c] = 0.f;
#pragma unroll
    for (int ks = 0; ks < 8; ++ks) {
        const int k0 = ks * 16 + tg * 2;
        uint32_t ah[4][4], al[4][4];
#pragma unroll
        for (int mf = 0; mf < 4; ++mf) {
            int r0 = wm * 64 + mf * 16 + g;
            ah[mf][0] = *(const uint32_t*)(Ah + r0 * SPITCH + k0);
            ah[mf][1] = *(const uint32_t*)(Ah + (r0 + 8) * SPITCH + k0);
            ah[mf][2] = *(const uint32_t*)(Ah + r0 * SPITCH + k0 + 8);
            ah[mf][3] = *(const uint32_t*)(Ah + (r0 + 8) * SPITCH + k0 + 8);
            al[mf][0] = *(const uint32_t*)(Al + r0 * SPITCH + k0);
            al[mf][1] = *(const uint32_t*)(Al + (r0 + 8) * SPITCH + k0);
            al[mf][2] = *(const uint32_t*)(Al + r0 * SPITCH + k0 + 8);
            al[mf][3] = *(const uint32_t*)(Al + (r0 + 8) * SPITCH + k0 + 8);
        }
#pragma unroll
        for (int nf = 0; nf < 4; ++nf) {
            int cb = wn * 32 + nf * 8 + g;
            uint32_t bh0 = *(const uint32_t*)(Bh + cb * SPITCH + k0);
            uint32_t bh1 = *(const uint32_t*)(Bh + cb * SPITCH + k0 + 8);
            uint32_t bl0 = *(const uint32_t*)(Bl + cb * SPITCH + k0);
            uint32_t bl1 = *(const uint32_t*)(Bl + cb * SPITCH + k0 + 8);
#pragma unroll
            for (int mf = 0; mf < 4; ++mf) {
                MMA_BF16(acc[mf][nf], ah[mf], bh0, bh1);
                MMA_BF16(acc[mf][nf], ah[mf], bl0, bl1);
                MMA_BF16(acc[mf][nf], al[mf], bh0, bh1);
            }
        }
    }
}

// ---------------------------------------------------------------------------
// att GEMM (all 3 n-tiles, A resident) + in-smem softmax + fp16 prob store
// ---------------------------------------------------------------------------
__global__ void __launch_bounds__(256) att_kernel() {
    extern __shared__ __nv_bfloat16 sm[];
    __nv_bfloat16* Ah = sm;
    __nv_bfloat16* Al = sm + TILE_H;
    __nv_bfloat16* Bh = sm + 2 * TILE_H;
    __nv_bfloat16* Bl = sm + 3 * TILE_H;
    __half* att_s = (__half*)(sm + 4 * TILE_H);

    const int tid = threadIdx.x;
    const int bm = blockIdx.x * 128;
    const int wid = tid >> 5, lane = tid & 31;
    const int wm = wid >> 2, wn = wid & 3;
    const int g = lane >> 2, tg = lane & 3;

    load_tile(g_xh, g_xl, Ah, Al, bm, NPIX, tid);

    for (int nt = 0; nt < 3; ++nt) {
        __syncthreads();
        load_tile(g_wqkv_h, g_wqkv_l, Bh, Bl, nt * 128, NQKV, tid);
        __syncthreads();
        float acc[4][4][4];
        mma_compute(Ah, Al, Bh, Bl, wm, wn, g, tg, acc);
#pragma unroll
        for (int mf = 0; mf < 4; ++mf) {
            int row = wm * 64 + mf * 16 + g;
#pragma unroll
            for (int nf = 0; nf < 4; ++nf) {
                int cc = nt * 128 + wn * 32 + nf * 8 + tg * 2;
                if (cc < NQKV) {
                    *(half2*)(att_s + row * APITCH + cc) =
                        __floats2half2_rn(acc[mf][nf][0], acc[mf][nf][1]);
                    *(half2*)(att_s + (row + 8) * APITCH + cc) =
                        __floats2half2_rn(acc[mf][nf][2], acc[mf][nf][3]);
                }
            }
        }
    }
    __syncthreads();

    // softmax over each 9-group, in smem
    const float scale = 0.17677669529663687f;  // 32^-0.5
    for (int t = tid; t < 128 * 36; t += 256) {
        int row = t / 36, grp = t % 36;
        __half* pp = att_s + row * APITCH + grp * 9;
        float v[9], m = -1e30f;
#pragma unroll
        for (int q = 0; q < 9; ++q) { v[q] = __half2float(pp[q]) * scale; m = fmaxf(m, v[q]); }
        float s = 0.f;
#pragma unroll
        for (int q = 0; q < 9; ++q) { v[q] = __expf(v[q] - m); s += v[q]; }
        float inv = 1.f / s;
#pragma unroll
        for (int q = 0; q < 9; ++q) pp[q] = __float2half_rn(v[q] * inv);
    }
    __syncthreads();

    // coalesced prob store
    for (int t = tid; t < 128 * NQKV; t += 256) {
        int row = t / NQKV, col = t - row * NQKV;
        g_attp[(size_t)(bm + row) * NQKV + col] = att_s[row * APITCH + col];
    }
}

// ---------------------------------------------------------------------------
// U GEMM: all 9 q-tiles with A resident, B double-buffered via cp.async
// ---------------------------------------------------------------------------
__global__ void __launch_bounds__(256) mma_u_kernel() {
    extern __shared__ __nv_bfloat16 sm[];
    __nv_bfloat16* Ah = sm;
    __nv_bfloat16* Al = sm + TILE_H;
    __nv_bfloat16* Bbuf = sm + 2 * TILE_H;   // two (h,l) tile pairs

    const int tid = threadIdx.x;
    const int bm = blockIdx.x * 128;
    const int wid = tid >> 5, lane = tid & 31;
    const int wm = wid >> 2, wn = wid & 3;
    const int g = lane >> 2, tg = lane & 3;

    load_tile_async(g_xh, g_xl, Ah, Al, bm, tid);
    load_tile_async(g_wv_h, g_wv_l, Bbuf, Bbuf + TILE_H, 0, tid);
    CP_COMMIT();

    for (int q = 0; q < 9; ++q) {
        __nv_bfloat16* Bh = Bbuf + (q & 1) * 2 * TILE_H;
        __nv_bfloat16* Bl = Bh + TILE_H;
        if (q < 8) {
            __nv_bfloat16* Ph = Bbuf + ((q + 1) & 1) * 2 * TILE_H;
            load_tile_async(g_wv_h, g_wv_l, Ph, Ph + TILE_H, (q + 1) * 128, tid);
            CP_COMMIT();
            CP_WAIT(1);
        } else {
            CP_WAIT(0);
        }
        __syncthreads();

        float acc[4][4][4];
        mma_compute(Ah, Al, Bh, Bl, wm, wn, g, tg, acc);

        __half* plane = g_u16 + (size_t)q * NPIX * CCH;
#pragma unroll
        for (int mf = 0; mf < 4; ++mf) {
            int row = bm + wm * 64 + mf * 16 + g;
#pragma unroll
            for (int nf = 0; nf < 4; ++nf) {
                int col = wn * 32 + nf * 8 + tg * 2;
                *(half2*)(plane + (size_t)row * 128 + col) =
                    __floats2half2_rn(acc[mf][nf][0], acc[mf][nf][1]);
                *(half2*)(plane + (size_t)(row + 8) * 128 + col) =
                    __floats2half2_rn(acc[mf][nf][2], acc[mf][nf][3]);
            }
        }
        __syncthreads();
    }
}

// ---------------------------------------------------------------------------
// projection GEMM: y (bf16 split) x wproj -> fp32 out
// ---------------------------------------------------------------------------
__global__ void __launch_bounds__(256) mma_proj_kernel(float* __restrict__ outp) {
    extern __shared__ __nv_bfloat16 sm[];
    __nv_bfloat16* Ah = sm;
    __nv_bfloat16* Al = sm + TILE_H;
    __nv_bfloat16* Bh = sm + 2 * TILE_H;
    __nv_bfloat16* Bl = sm + 3 * TILE_H;

    const int tid = threadIdx.x;
    const int bm = blockIdx.x * 128;
    const int wid = tid >> 5, lane = tid & 31;
    const int wm = wid >> 2, wn = wid & 3;
    const int g = lane >> 2, tg = lane & 3;

    load_tile(g_yh, g_yl, Ah, Al, bm, NPIX, tid);
    load_tile(g_wpr_h, g_wpr_l, Bh, Bl, 0, CCH, tid);
    __syncthreads();
    float acc[4][4][4];
    mma_compute(Ah, Al, Bh, Bl, wm, wn, g, tg, acc);
#pragma unroll
    for (int mf = 0; mf < 4; ++mf) {
        int row = bm + wm * 64 + mf * 16 + g;
#pragma unroll
        for (int nf = 0; nf < 4; ++nf) {
            int col = wn * 32 + nf * 8 + tg * 2;
            *(float2*)&outp[(size_t)row * 128 + col] =
                make_float2(acc[mf][nf][0], acc[mf][nf][1]);
            *(float2*)&outp[(size_t)(row + 8) * 128 + col] =
                make_float2(acc[mf][nf][2], acc[mf][nf][3]);
        }
    }
}

// ---------------------------------------------------------------------------
// combine: out[g][p][c] = sum_q att[g][h(c)][p][q] * U[g+off(q)][q][c]
// 4 pixels per block, 64 threads / pixel, half2 channels
// ---------------------------------------------------------------------------
__global__ void __launch_bounds__(256) combine_kernel() {
    const int sub = threadIdx.x >> 6;        // 0..3
    const int c2  = threadIdx.x & 63;        // half2 lane (channels 2*c2, 2*c2+1)
    const int g   = blockIdx.x * 4 + sub;
    __shared__ float att_s[4][NQKV];
    const __half* ap = g_attp + (size_t)g * NQKV;
    for (int t = c2; t < 162; t += 64) {
        float2 f = __half22float2(*(const half2*)(ap + t * 2));
        att_s[sub][t * 2] = f.x;
        att_s[sub][t * 2 + 1] = f.y;
    }
    __syncthreads();

    const int b = g >> 14;
    const int n = g & (HW - 1);
    const int i = n >> 7, j = n & 127;
    float2 v[9];
#pragma unroll
    for (int q = 0; q < 9; ++q) {
        int ii = i + q / 3 - 1;
        int jj = j + q % 3 - 1;
        bool valid = ((unsigned)ii < 128u) && ((unsigned)jj < 128u);
        v[q] = valid ? __half22float2(*(const half2*)&g_u16[
                   ((size_t)q * NPIX + ((b << 14) + (ii << 7) + jj)) * 128 + c2 * 2])
                     : make_float2(0.f, 0.f);
    }
    const float* ah = att_s[sub] + (c2 >> 4) * 81;
    float2 acc[9];
#pragma unroll
    for (int p2 = 0; p2 < 9; ++p2) acc[p2] = make_float2(0.f, 0.f);
#pragma unroll
    for (int q = 0; q < 9; ++q) {
        float2 vq = v[q];
#pragma unroll
        for (int p2 = 0; p2 < 9; ++p2) {
            float w = ah[p2 * 9 + q];
            acc[p2].x += w * vq.x;
            acc[p2].y += w * vq.y;
        }
    }
    __half* op = g_out16 + (size_t)g * NV + c2 * 2;
#pragma unroll
    for (int p2 = 0; p2 < 9; ++p2)
        *(half2*)(op + (p2 << 7)) = __floats2half2_rn(acc[p2].x, acc[p2].y);
}

// ---------------------------------------------------------------------------
// fold (gather), 4 channels/thread; writes bf16 hi/lo y
// ---------------------------------------------------------------------------
__global__ void fold_kernel() {
    int idx = blockIdx.x * blockDim.x + threadIdx.x;  // over NPIX*32
    if (idx >= NPIX * 32) return;
    int c4 = idx & 31;                 // channels 4*c4 .. 4*c4+3
    int g = idx >> 5;
    int b = g >> 14, n = g & (HW - 1);
    int i = n >> 7, j = n & 127;
    float a0 = 0.f, a1 = 0.f, a2 = 0.f, a3 = 0.f;
#pragma unroll
    for (int dr = -1; dr <= 1; ++dr) {
#pragma unroll
        for (int ds = -1; ds <= 1; ++ds) {
            int r = i + dr, s = j + ds;
            if ((unsigned)r < 128u && (unsigned)s < 128u) {
                int gp = (b << 14) + (r << 7) + s;
                int p2 = (1 - dr) * 3 + (1 - ds);
                const __half* src = &g_out16[(size_t)gp * NV + (p2 << 7) + c4 * 4];
                uint2 raw = *(const uint2*)src;
                float2 f0 = __half22float2(*(half2*)&raw.x);
                float2 f1 = __half22float2(*(half2*)&raw.y);
                a0 += f0.x; a1 += f0.y; a2 += f1.x; a3 += f1.y;
            }
        }
    }
    __nv_bfloat16 h0, l0, h1, l1, h2, l2, h3, l3;
    split_bf16(a0, h0, l0);
    split_bf16(a1, h1, l1);
    split_bf16(a2, h2, l2);
    split_bf16(a3, h3, l3);
    size_t o = (size_t)g * 128 + c4 * 4;
    __nv_bfloat162 hh0(h0, h1), hh1(h2, h3), ll0(l0, l1), ll1(l2, l3);
    *(uint2*)&g_yh[o] = make_uint2(*(uint32_t*)&hh0, *(uint32_t*)&hh1);
    *(uint2*)&g_yl[o] = make_uint2(*(uint32_t*)&ll0, *(uint32_t*)&ll1);
}

// ---------------------------------------------------------------------------
extern "C" void kernel_launch(void* const* d_in, const int* in_sizes, int n_in,
                              void* d_out, int out_size) {
    const float* x     = (const float*)d_in[0];
    const float* wqkv  = (const float*)d_in[1];
    const float* wv    = (const float*)d_in[2];
    const float* wproj = (const float*)d_in[3];
    float* out = (float*)d_out;

    cudaFuncSetAttribute(att_kernel,      cudaFuncAttributeMaxDynamicSharedMemorySize, ATT_SMEM);
    cudaFuncSetAttribute(mma_u_kernel,    cudaFuncAttributeMaxDynamicSharedMemorySize, U_SMEM);
    cudaFuncSetAttribute(mma_proj_kernel, cudaFuncAttributeMaxDynamicSharedMemorySize, GEMM_SMEM);

    conv_x_kernel<<<(NPIX * 64 + 255) / 256, 256>>>(x);
    conv_w_kernel<<<(NV * CCH + 255) / 256, 256>>>(wqkv, wv, wproj);

    att_kernel<<<512, 256, ATT_SMEM>>>();
    mma_u_kernel<<<512, 256, U_SMEM>>>();
    combine_kernel<<<NPIX / 4, 256>>>();
    fold_kernel<<<(NPIX * 32 + 255) / 256, 256>>>();
    mma_proj_kernel<<<512, 256, GEMM_SMEM>>>(out);
}

// round 7
// speedup vs baseline: 2.1853x; 1.0242x over previous
#include <cuda_runtime.h>
#include <cuda_bf16.h>
#include <cuda_fp16.h>
#include <cstdint>

// Problem constants
#define NPIX   65536      // B*H*W = 4*128*128
#define CCH    128        // channels
#define NQKV   324        // 81 * 4 heads
#define HW     16384      // H*W per image
#define NV     1152       // 9 * 128
#define SPITCH 136        // smem row pitch (halves)
#define APITCH 328        // att smem row pitch (halves)
#define TILE_H (128 * SPITCH)            // halves per tile buffer

#define GEMM_SMEM (4 * TILE_H * 2)                 // A(h,l) + B(h,l)
#define U_SMEM    (6 * TILE_H * 2)                 // A(h,l) + 2x B(h,l)
#define ATT_SMEM  (GEMM_SMEM + 128 * APITCH * 2)

// ---------------------------------------------------------------------------
// Scratch (device globals)
// ---------------------------------------------------------------------------
__device__ __nv_bfloat16 g_xh[(size_t)NPIX * CCH];
__device__ __nv_bfloat16 g_xl[(size_t)NPIX * CCH];
__device__ __nv_bfloat16 g_wqkv_h[NQKV * CCH];
__device__ __nv_bfloat16 g_wqkv_l[NQKV * CCH];
__device__ __nv_bfloat16 g_wv_h[NV * CCH];
__device__ __nv_bfloat16 g_wv_l[NV * CCH];
__device__ __nv_bfloat16 g_wpr_h[CCH * CCH];
__device__ __nv_bfloat16 g_wpr_l[CCH * CCH];
__device__ __half g_attp[(size_t)NPIX * NQKV];   // softmax probs (fp16)
__device__ __half g_u16[(size_t)9 * NPIX * CCH]; // U planes [q][g][c]
__device__ __half g_out16[(size_t)NPIX * NV];    // combine out [g][p][c]
__device__ __nv_bfloat16 g_yh[(size_t)NPIX * CCH];
__device__ __nv_bfloat16 g_yl[(size_t)NPIX * CCH];

// ---------------------------------------------------------------------------
__device__ __forceinline__ void split_bf16(float v, __nv_bfloat16& h, __nv_bfloat16& l) {
    h = __float2bfloat16_rn(v);
    l = __float2bfloat16_rn(v - __bfloat162float(h));
}

__global__ void conv_x_kernel(const float* __restrict__ x) {
    int idx = blockIdx.x * blockDim.x + threadIdx.x;   // over NPIX*64
    if (idx >= NPIX * 64) return;
    float2 f = ((const float2*)x)[idx];
    __nv_bfloat16 hx, lx, hy, ly;
    split_bf16(f.x, hx, lx);
    split_bf16(f.y, hy, ly);
    ((__nv_bfloat162*)g_xh)[idx] = __nv_bfloat162(hx, hy);
    ((__nv_bfloat162*)g_xl)[idx] = __nv_bfloat162(lx, ly);
}

__global__ void conv_w_kernel(const float* __restrict__ wqkv,
                              const float* __restrict__ wv,
                              const float* __restrict__ wproj) {
    int t = blockIdx.x * blockDim.x + threadIdx.x;
    if (t < NQKV * CCH) split_bf16(wqkv[t], g_wqkv_h[t], g_wqkv_l[t]);
    if (t < NV * CCH)   split_bf16(wv[t],   g_wv_h[t],   g_wv_l[t]);
    if (t < CCH * CCH)  split_bf16(wproj[t], g_wpr_h[t], g_wpr_l[t]);
}

// ---------------------------------------------------------------------------
#define MMA_BF16(d, a, b0v, b1v)                                              \
    asm volatile("mma.sync.aligned.m16n8k16.row.col.f32.bf16.bf16.f32 "       \
                 "{%0,%1,%2,%3},{%4,%5,%6,%7},{%8,%9},{%0,%1,%2,%3};"         \
                 : "+f"(d[0]), "+f"(d[1]), "+f"(d[2]), "+f"(d[3])             \
                 : "r"(a[0]), "r"(a[1]), "r"(a[2]), "r"(a[3]),                \
                   "r"(b0v), "r"(b1v))

#define LDSM4(r, addr)                                                        \
    asm volatile("ldmatrix.sync.aligned.m8n8.x4.shared.b16 {%0,%1,%2,%3}, [%4];" \
                 : "=r"((r)[0]), "=r"((r)[1]), "=r"((r)[2]), "=r"((r)[3])     \
                 : "r"(addr))

__device__ __forceinline__ void cp_async16(void* sptr, const void* gptr) {
    uint32_t saddr = (uint32_t)__cvta_generic_to_shared(sptr);
    asm volatile("cp.async.cg.shared.global [%0], [%1], 16;" :: "r"(saddr), "l"(gptr));
}
#define CP_COMMIT()  asm volatile("cp.async.commit_group;")
#define CP_WAIT(n)   asm volatile("cp.async.wait_group %0;" :: "n"(n))

// synchronous tile pair load (bounds-checked)
__device__ __forceinline__ void load_tile(const __nv_bfloat16* __restrict__ Hg,
                                          const __nv_bfloat16* __restrict__ Lg,
                                          __nv_bfloat16* Hs, __nv_bfloat16* Ls,
                                          int base_row, int row_limit, int tid) {
#pragma unroll
    for (int it = 0; it < 8; ++it) {
        int idx = tid + it * 256;
        int row = idx >> 4, f4 = idx & 15;
        int grow = base_row + row;
        float4 h4 = make_float4(0.f, 0.f, 0.f, 0.f), l4 = h4;
        if (grow < row_limit) {
            h4 = ((const float4*)(Hg + (size_t)grow * 128))[f4];
            l4 = ((const float4*)(Lg + (size_t)grow * 128))[f4];
        }
        *(float4*)(Hs + row * SPITCH + f4 * 8) = h4;
        *(float4*)(Ls + row * SPITCH + f4 * 8) = l4;
    }
}

// async tile pair load (no bounds: rows guaranteed in range)
__device__ __forceinline__ void load_tile_async(const __nv_bfloat16* __restrict__ Hg,
                                                const __nv_bfloat16* __restrict__ Lg,
                                                __nv_bfloat16* Hs, __nv_bfloat16* Ls,
                                                int base_row, int tid) {
#pragma unroll
    for (int it = 0; it < 8; ++it) {
        int idx = tid + it * 256;
        int row = idx >> 4, f4 = idx & 15;
        cp_async16(Hs + row * SPITCH + f4 * 8, Hg + (size_t)(base_row + row) * 128 + f4 * 8);
        cp_async16(Ls + row * SPITCH + f4 * 8, Lg + (size_t)(base_row + row) * 128 + f4 * 8);
    }
}

// ---------------------------------------------------------------------------
// 8-kstep MMA over resident smem tiles using ldmatrix; acc[4][4][4]
// A-fragment lane addr: row = wm*64 + mf*16 + (lane&15), colhalf = (lane>>4)*8
// B-fragment lane addr (per 2-nf pair): row = wn*32 + np*16 + ((lane>>4)&1)*8 + (lane&7),
//                                       colhalf = ((lane>>3)&1)*8
// ---------------------------------------------------------------------------
__device__ __forceinline__ void mma_compute(const __nv_bfloat16* Ah, const __nv_bfloat16* Al,
                                            const __nv_bfloat16* Bh, const __nv_bfloat16* Bl,
                                            int wm, int wn, int lane,
                                            float acc[4][4][4]) {
#pragma unroll
    for (int a = 0; a < 4; ++a)
#pragma unroll
        for (int b = 0; b < 4; ++b)
#pragma unroll
            for (int c = 0; c < 4; ++c) acc[a][b][c] = 0.f;

    const uint32_t sAh = (uint32_t)__cvta_generic_to_shared(Ah);
    const uint32_t sAl = (uint32_t)__cvta_generic_to_shared(Al);
    const uint32_t sBh = (uint32_t)__cvta_generic_to_shared(Bh);
    const uint32_t sBl = (uint32_t)__cvta_generic_to_shared(Bl);

    const uint32_t aoff =
        (uint32_t)(((wm * 64 + (lane & 15)) * SPITCH + (lane >> 4) * 8) * 2);
    const uint32_t boff =
        (uint32_t)(((wn * 32 + ((lane >> 4) & 1) * 8 + (lane & 7)) * SPITCH +
                    ((lane >> 3) & 1) * 8) * 2);

#pragma unroll
    for (int ks = 0; ks < 8; ++ks) {
        const uint32_t kb = ks * 32;           // 16 halves = 32 bytes per kstep
        uint32_t ah[4][4], al[4][4];
#pragma unroll
        for (int mf = 0; mf < 4; ++mf) {
            const uint32_t mo = mf * (16 * SPITCH * 2);
            LDSM4(ah[mf], sAh + mo + aoff + kb);
            LDSM4(al[mf], sAl + mo + aoff + kb);
        }
        uint32_t bh[2][4], bl[2][4];
#pragma unroll
        for (int np = 0; np < 2; ++np) {
            const uint32_t no = np * (16 * SPITCH * 2);
            LDSM4(bh[np], sBh + no + boff + kb);
            LDSM4(bl[np], sBl + no + boff + kb);
        }
#pragma unroll
        for (int nf = 0; nf < 4; ++nf) {
            uint32_t bh0 = bh[nf >> 1][(nf & 1) * 2];
            uint32_t bh1 = bh[nf >> 1][(nf & 1) * 2 + 1];
            uint32_t bl0 = bl[nf >> 1][(nf & 1) * 2];
            uint32_t bl1 = bl[nf >> 1][(nf & 1) * 2 + 1];
#pragma unroll
            for (int mf = 0; mf < 4; ++mf) {
                MMA_BF16(acc[mf][nf], ah[mf], bh0, bh1);
                MMA_BF16(acc[mf][nf], ah[mf], bl0, bl1);
                MMA_BF16(acc[mf][nf], al[mf], bh0, bh1);
            }
        }
    }
}

// ---------------------------------------------------------------------------
// att GEMM (all 3 n-tiles, A resident) + in-smem softmax + fp16 prob store
// ---------------------------------------------------------------------------
__global__ void __launch_bounds__(256) att_kernel() {
    extern __shared__ __nv_bfloat16 sm[];
    __nv_bfloat16* Ah = sm;
    __nv_bfloat16* Al = sm + TILE_H;
    __nv_bfloat16* Bh = sm + 2 * TILE_H;
    __nv_bfloat16* Bl = sm + 3 * TILE_H;
    __half* att_s = (__half*)(sm + 4 * TILE_H);

    const int tid = threadIdx.x;
    const int bm = blockIdx.x * 128;
    const int wid = tid >> 5, lane = tid & 31;
    const int wm = wid >> 2, wn = wid & 3;
    const int g = lane >> 2, tg = lane & 3;

    load_tile(g_xh, g_xl, Ah, Al, bm, NPIX, tid);

    for (int nt = 0; nt < 3; ++nt) {
        __syncthreads();
        load_tile(g_wqkv_h, g_wqkv_l, Bh, Bl, nt * 128, NQKV, tid);
        __syncthreads();
        float acc[4][4][4];
        mma_compute(Ah, Al, Bh, Bl, wm, wn, lane, acc);
#pragma unroll
        for (int mf = 0; mf < 4; ++mf) {
            int row = wm * 64 + mf * 16 + g;
#pragma unroll
            for (int nf = 0; nf < 4; ++nf) {
                int cc = nt * 128 + wn * 32 + nf * 8 + tg * 2;
                if (cc < NQKV) {
                    *(half2*)(att_s + row * APITCH + cc) =
                        __floats2half2_rn(acc[mf][nf][0], acc[mf][nf][1]);
                    *(half2*)(att_s + (row + 8) * APITCH + cc) =
                        __floats2half2_rn(acc[mf][nf][2], acc[mf][nf][3]);
                }
            }
        }
    }
    __syncthreads();

    // softmax over each 9-group, in smem
    const float scale = 0.17677669529663687f;  // 32^-0.5
    for (int t = tid; t < 128 * 36; t += 256) {
        int row = t / 36, grp = t % 36;
        __half* pp = att_s + row * APITCH + grp * 9;
        float v[9], m = -1e30f;
#pragma unroll
        for (int q = 0; q < 9; ++q) { v[q] = __half2float(pp[q]) * scale; m = fmaxf(m, v[q]); }
        float s = 0.f;
#pragma unroll
        for (int q = 0; q < 9; ++q) { v[q] = __expf(v[q] - m); s += v[q]; }
        float inv = 1.f / s;
#pragma unroll
        for (int q = 0; q < 9; ++q) pp[q] = __float2half_rn(v[q] * inv);
    }
    __syncthreads();

    // coalesced prob store
    for (int t = tid; t < 128 * NQKV; t += 256) {
        int row = t / NQKV, col = t - row * NQKV;
        g_attp[(size_t)(bm + row) * NQKV + col] = att_s[row * APITCH + col];
    }
}

// ---------------------------------------------------------------------------
// U GEMM: all 9 q-tiles with A resident, B double-buffered via cp.async
// ---------------------------------------------------------------------------
__global__ void __launch_bounds__(256) mma_u_kernel() {
    extern __shared__ __nv_bfloat16 sm[];
    __nv_bfloat16* Ah = sm;
    __nv_bfloat16* Al = sm + TILE_H;
    __nv_bfloat16* Bbuf = sm + 2 * TILE_H;   // two (h,l) tile pairs

    const int tid = threadIdx.x;
    const int bm = blockIdx.x * 128;
    const int wid = tid >> 5, lane = tid & 31;
    const int wm = wid >> 2, wn = wid & 3;
    const int g = lane >> 2, tg = lane & 3;

    load_tile_async(g_xh, g_xl, Ah, Al, bm, tid);
    load_tile_async(g_wv_h, g_wv_l, Bbuf, Bbuf + TILE_H, 0, tid);
    CP_COMMIT();

    for (int q = 0; q < 9; ++q) {
        __nv_bfloat16* Bh = Bbuf + (q & 1) * 2 * TILE_H;
        __nv_bfloat16* Bl = Bh + TILE_H;
        if (q < 8) {
            __nv_bfloat16* Ph = Bbuf + ((q + 1) & 1) * 2 * TILE_H;
            load_tile_async(g_wv_h, g_wv_l, Ph, Ph + TILE_H, (q + 1) * 128, tid);
            CP_COMMIT();
            CP_WAIT(1);
        } else {
            CP_WAIT(0);
        }
        __syncthreads();

        float acc[4][4][4];
        mma_compute(Ah, Al, Bh, Bl, wm, wn, lane, acc);

        __half* plane = g_u16 + (size_t)q * NPIX * CCH;
#pragma unroll
        for (int mf = 0; mf < 4; ++mf) {
            int row = bm + wm * 64 + mf * 16 + g;
#pragma unroll
            for (int nf = 0; nf < 4; ++nf) {
                int col = wn * 32 + nf * 8 + tg * 2;
                *(half2*)(plane + (size_t)row * 128 + col) =
                    __floats2half2_rn(acc[mf][nf][0], acc[mf][nf][1]);
                *(half2*)(plane + (size_t)(row + 8) * 128 + col) =
                    __floats2half2_rn(acc[mf][nf][2], acc[mf][nf][3]);
            }
        }
        __syncthreads();
    }
}

// ---------------------------------------------------------------------------
// projection GEMM: y (bf16 split) x wproj -> fp32 out
// ---------------------------------------------------------------------------
__global__ void __launch_bounds__(256) mma_proj_kernel(float* __restrict__ outp) {
    extern __shared__ __nv_bfloat16 sm[];
    __nv_bfloat16* Ah = sm;
    __nv_bfloat16* Al = sm + TILE_H;
    __nv_bfloat16* Bh = sm + 2 * TILE_H;
    __nv_bfloat16* Bl = sm + 3 * TILE_H;

    const int tid = threadIdx.x;
    const int bm = blockIdx.x * 128;
    const int wid = tid >> 5, lane = tid & 31;
    const int wm = wid >> 2, wn = wid & 3;
    const int g = lane >> 2, tg = lane & 3;

    load_tile(g_yh, g_yl, Ah, Al, bm, NPIX, tid);
    load_tile(g_wpr_h, g_wpr_l, Bh, Bl, 0, CCH, tid);
    __syncthreads();
    float acc[4][4][4];
    mma_compute(Ah, Al, Bh, Bl, wm, wn, lane, acc);
#pragma unroll
    for (int mf = 0; mf < 4; ++mf) {
        int row = bm + wm * 64 + mf * 16 + g;
#pragma unroll
        for (int nf = 0; nf < 4; ++nf) {
            int col = wn * 32 + nf * 8 + tg * 2;
            *(float2*)&outp[(size_t)row * 128 + col] =
                make_float2(acc[mf][nf][0], acc[mf][nf][1]);
            *(float2*)&outp[(size_t)(row + 8) * 128 + col] =
                make_float2(acc[mf][nf][2], acc[mf][nf][3]);
        }
    }
}

// ---------------------------------------------------------------------------
// combine: out[g][p][c] = sum_q att[g][h(c)][p][q] * U[g+off(q)][q][c]
// 4 pixels per block, 64 threads / pixel, half2 channels
// ---------------------------------------------------------------------------
__global__ void __launch_bounds__(256) combine_kernel() {
    const int sub = threadIdx.x >> 6;        // 0..3
    const int c2  = threadIdx.x & 63;        // half2 lane (channels 2*c2, 2*c2+1)
    const int g   = blockIdx.x * 4 + sub;
    __shared__ float att_s[4][NQKV];
    const __half* ap = g_attp + (size_t)g * NQKV;
    for (int t = c2; t < 162; t += 64) {
        float2 f = __half22float2(*(const half2*)(ap + t * 2));
        att_s[sub][t * 2] = f.x;
        att_s[sub][t * 2 + 1] = f.y;
    }
    __syncthreads();

    const int b = g >> 14;
    const int n = g & (HW - 1);
    const int i = n >> 7, j = n & 127;
    float2 v[9];
#pragma unroll
    for (int q = 0; q < 9; ++q) {
        int ii = i + q / 3 - 1;
        int jj = j + q % 3 - 1;
        bool valid = ((unsigned)ii < 128u) && ((unsigned)jj < 128u);
        v[q] = valid ? __half22float2(*(const half2*)&g_u16[
                   ((size_t)q * NPIX + ((b << 14) + (ii << 7) + jj)) * 128 + c2 * 2])
                     : make_float2(0.f, 0.f);
    }
    const float* ah = att_s[sub] + (c2 >> 4) * 81;
    float2 acc[9];
#pragma unroll
    for (int p2 = 0; p2 < 9; ++p2) acc[p2] = make_float2(0.f, 0.f);
#pragma unroll
    for (int q = 0; q < 9; ++q) {
        float2 vq = v[q];
#pragma unroll
        for (int p2 = 0; p2 < 9; ++p2) {
            float w = ah[p2 * 9 + q];
            acc[p2].x += w * vq.x;
            acc[p2].y += w * vq.y;
        }
    }
    __half* op = g_out16 + (size_t)g * NV + c2 * 2;
#pragma unroll
    for (int p2 = 0; p2 < 9; ++p2)
        *(half2*)(op + (p2 << 7)) = __floats2half2_rn(acc[p2].x, acc[p2].y);
}

// ---------------------------------------------------------------------------
// fold (gather), 4 channels/thread; writes bf16 hi/lo y
// ---------------------------------------------------------------------------
__global__ void fold_kernel() {
    int idx = blockIdx.x * blockDim.x + threadIdx.x;  // over NPIX*32
    if (idx >= NPIX * 32) return;
    int c4 = idx & 31;                 // channels 4*c4 .. 4*c4+3
    int g = idx >> 5;
    int b = g >> 14, n = g & (HW - 1);
    int i = n >> 7, j = n & 127;
    float a0 = 0.f, a1 = 0.f, a2 = 0.f, a3 = 0.f;
#pragma unroll
    for (int dr = -1; dr <= 1; ++dr) {
#pragma unroll
        for (int ds = -1; ds <= 1; ++ds) {
            int r = i + dr, s = j + ds;
            if ((unsigned)r < 128u && (unsigned)s < 128u) {
                int gp = (b << 14) + (r << 7) + s;
                int p2 = (1 - dr) * 3 + (1 - ds);
                const __half* src = &g_out16[(size_t)gp * NV + (p2 << 7) + c4 * 4];
                uint2 raw = *(const uint2*)src;
                float2 f0 = __half22float2(*(half2*)&raw.x);
                float2 f1 = __half22float2(*(half2*)&raw.y);
                a0 += f0.x; a1 += f0.y; a2 += f1.x; a3 += f1.y;
            }
        }
    }
    __nv_bfloat16 h0, l0, h1, l1, h2, l2, h3, l3;
    split_bf16(a0, h0, l0);
    split_bf16(a1, h1, l1);
    split_bf16(a2, h2, l2);
    split_bf16(a3, h3, l3);
    size_t o = (size_t)g * 128 + c4 * 4;
    __nv_bfloat162 hh0(h0, h1), hh1(h2, h3), ll0(l0, l1), ll1(l2, l3);
    *(uint2*)&g_yh[o] = make_uint2(*(uint32_t*)&hh0, *(uint32_t*)&hh1);
    *(uint2*)&g_yl[o] = make_uint2(*(uint32_t*)&ll0, *(uint32_t*)&ll1);
}

// ---------------------------------------------------------------------------
extern "C" void kernel_launch(void* const* d_in, const int* in_sizes, int n_in,
                              void* d_out, int out_size) {
    const float* x     = (const float*)d_in[0];
    const float* wqkv  = (const float*)d_in[1];
    const float* wv    = (const float*)d_in[2];
    const float* wproj = (const float*)d_in[3];
    float* out = (float*)d_out;

    cudaFuncSetAttribute(att_kernel,      cudaFuncAttributeMaxDynamicSharedMemorySize, ATT_SMEM);
    cudaFuncSetAttribute(mma_u_kernel,    cudaFuncAttributeMaxDynamicSharedMemorySize, U_SMEM);
    cudaFuncSetAttribute(mma_proj_kernel, cudaFuncAttributeMaxDynamicSharedMemorySize, GEMM_SMEM);

    conv_x_kernel<<<(NPIX * 64 + 255) / 256, 256>>>(x);
    conv_w_kernel<<<(NV * CCH + 255) / 256, 256>>>(wqkv, wv, wproj);

    att_kernel<<<512, 256, ATT_SMEM>>>();
    mma_u_kernel<<<512, 256, U_SMEM>>>();
    combine_kernel<<<NPIX / 4, 256>>>();
    fold_kernel<<<(NPIX * 32 + 255) / 256, 256>>>();
    mma_proj_kernel<<<512, 256, GEMM_SMEM>>>(out);
}

// round 11
// speedup vs baseline: 2.2579x; 1.0333x over previous
#include <cuda_runtime.h>
#include <cuda_bf16.h>
#include <cuda_fp16.h>
#include <cstdint>

// Problem constants
#define NPIX   65536      // B*H*W = 4*128*128
#define CCH    128        // channels
#define NQKV   324        // 81 * 4 heads
#define HW     16384      // H*W per image
#define NV     1152       // 9 * 128
#define SPITCH 136        // smem row pitch (halves)
#define APITCH 328        // att smem row pitch (halves)
#define TILE_H   (128 * SPITCH)          // halves per 128-row tile
#define TILE64_H (64 * SPITCH)           // halves per 64-row tile

#define ATT_SMEM  (4 * TILE_H * 2 + 128 * APITCH * 2)        // MF=4 kernel
#define G64_SMEM  ((2 * TILE64_H + 2 * TILE_H) * 2)          // A64(h,l)+B128(h,l)

// ---------------------------------------------------------------------------
// Scratch (device globals)
// ---------------------------------------------------------------------------
__device__ __nv_bfloat16 g_xh[(size_t)NPIX * CCH];
__device__ __nv_bfloat16 g_xl[(size_t)NPIX * CCH];
__device__ __nv_bfloat16 g_wqkv_h[NQKV * CCH];
__device__ __nv_bfloat16 g_wqkv_l[NQKV * CCH];
__device__ __nv_bfloat16 g_wv_h[NV * CCH];
__device__ __nv_bfloat16 g_wv_l[NV * CCH];
__device__ __nv_bfloat16 g_wpr_h[CCH * CCH];
__device__ __nv_bfloat16 g_wpr_l[CCH * CCH];
__device__ __half g_attp[(size_t)NPIX * NQKV];   // softmax probs (fp16)
__device__ __half g_u16[(size_t)9 * NPIX * CCH]; // U planes [q][g][c]
__device__ __half g_out16[(size_t)NPIX * NV];    // combine out [g][p][c]
__device__ __nv_bfloat16 g_yh[(size_t)NPIX * CCH];
__device__ __nv_bfloat16 g_yl[(size_t)NPIX * CCH];

// ---------------------------------------------------------------------------
__device__ __forceinline__ void split_bf16(float v, __nv_bfloat16& h, __nv_bfloat16& l) {
    h = __float2bfloat16_rn(v);
    l = __float2bfloat16_rn(v - __bfloat162float(h));
}

__global__ void conv_x_kernel(const float* __restrict__ x) {
    int idx = blockIdx.x * blockDim.x + threadIdx.x;   // over NPIX*64
    if (idx >= NPIX * 64) return;
    float2 f = ((const float2*)x)[idx];
    __nv_bfloat16 hx, lx, hy, ly;
    split_bf16(f.x, hx, lx);
    split_bf16(f.y, hy, ly);
    ((__nv_bfloat162*)g_xh)[idx] = __nv_bfloat162(hx, hy);
    ((__nv_bfloat162*)g_xl)[idx] = __nv_bfloat162(lx, ly);
}

__global__ void conv_w_kernel(const float* __restrict__ wqkv,
                              const float* __restrict__ wv,
                              const float* __restrict__ wproj) {
    int t = blockIdx.x * blockDim.x + threadIdx.x;
    if (t < NQKV * CCH) split_bf16(wqkv[t], g_wqkv_h[t], g_wqkv_l[t]);
    if (t < NV * CCH)   split_bf16(wv[t],   g_wv_h[t],   g_wv_l[t]);
    if (t < CCH * CCH)  split_bf16(wproj[t], g_wpr_h[t], g_wpr_l[t]);
}

// ---------------------------------------------------------------------------
#define MMA_BF16(d, a, b0v, b1v)                                              \
    asm volatile("mma.sync.aligned.m16n8k16.row.col.f32.bf16.bf16.f32 "       \
                 "{%0,%1,%2,%3},{%4,%5,%6,%7},{%8,%9},{%0,%1,%2,%3};"         \
                 : "+f"(d[0]), "+f"(d[1]), "+f"(d[2]), "+f"(d[3])             \
                 : "r"(a[0]), "r"(a[1]), "r"(a[2]), "r"(a[3]),                \
                   "r"(b0v), "r"(b1v))

#define LDSM4(r, addr)                                                        \
    asm volatile("ldmatrix.sync.aligned.m8n8.x4.shared.b16 {%0,%1,%2,%3}, [%4];" \
                 : "=r"((r)[0]), "=r"((r)[1]), "=r"((r)[2]), "=r"((r)[3])     \
                 : "r"(addr))

__device__ __forceinline__ void cp_async16(void* sptr, const void* gptr) {
    uint32_t saddr = (uint32_t)__cvta_generic_to_shared(sptr);
    asm volatile("cp.async.cg.shared.global [%0], [%1], 16;" :: "r"(saddr), "l"(gptr));
}
#define CP_COMMIT()  asm volatile("cp.async.commit_group;")
#define CP_WAIT0()   asm volatile("cp.async.wait_group 0;")

// synchronous tile pair load (bounds-checked), ROWS rows
template <int ROWS>
__device__ __forceinline__ void load_tile(const __nv_bfloat16* __restrict__ Hg,
                                          const __nv_bfloat16* __restrict__ Lg,
                                          __nv_bfloat16* Hs, __nv_bfloat16* Ls,
                                          int base_row, int row_limit, int tid) {
#pragma unroll
    for (int it = 0; it < ROWS / 16; ++it) {
        int idx = tid + it * 256;
        int row = idx >> 4, f4 = idx & 15;
        int grow = base_row + row;
        float4 h4 = make_float4(0.f, 0.f, 0.f, 0.f), l4 = h4;
        if (grow < row_limit) {
            h4 = ((const float4*)(Hg + (size_t)grow * 128))[f4];
            l4 = ((const float4*)(Lg + (size_t)grow * 128))[f4];
        }
        *(float4*)(Hs + row * SPITCH + f4 * 8) = h4;
        *(float4*)(Ls + row * SPITCH + f4 * 8) = l4;
    }
}

// async tile pair load (no bounds), ROWS rows
template <int ROWS>
__device__ __forceinline__ void load_tile_async(const __nv_bfloat16* __restrict__ Hg,
                                                const __nv_bfloat16* __restrict__ Lg,
                                                __nv_bfloat16* Hs, __nv_bfloat16* Ls,
                                                int base_row, int tid) {
#pragma unroll
    for (int it = 0; it < ROWS / 16; ++it) {
        int idx = tid + it * 256;
        int row = idx >> 4, f4 = idx & 15;
        cp_async16(Hs + row * SPITCH + f4 * 8, Hg + (size_t)(base_row + row) * 128 + f4 * 8);
        cp_async16(Ls + row * SPITCH + f4 * 8, Lg + (size_t)(base_row + row) * 128 + f4 * 8);
    }
}

// ---------------------------------------------------------------------------
// 8-kstep MMA over resident smem tiles using ldmatrix; acc[MF][4][4]
// warp rows: wm covers MF*16 rows; warp cols: wn covers 32 cols
// ---------------------------------------------------------------------------
template <int MF>
__device__ __forceinline__ void mma_compute(const __nv_bfloat16* Ah, const __nv_bfloat16* Al,
                                            const __nv_bfloat16* Bh, const __nv_bfloat16* Bl,
                                            int wm, int wn, int lane,
                                            float acc[MF][4][4]) {
#pragma unroll
    for (int a = 0; a < MF; ++a)
#pragma unroll
        for (int b = 0; b < 4; ++b)
#pragma unroll
            for (int c = 0; c < 4; ++c) acc[a][b][c] = 0.f;

    const uint32_t sAh = (uint32_t)__cvta_generic_to_shared(Ah);
    const uint32_t sAl = (uint32_t)__cvta_generic_to_shared(Al);
    const uint32_t sBh = (uint32_t)__cvta_generic_to_shared(Bh);
    const uint32_t sBl = (uint32_t)__cvta_generic_to_shared(Bl);

    const uint32_t aoff =
        (uint32_t)(((wm * (MF * 16) + (lane & 15)) * SPITCH + (lane >> 4) * 8) * 2);
    const uint32_t boff =
        (uint32_t)(((wn * 32 + ((lane >> 4) & 1) * 8 + (lane & 7)) * SPITCH +
                    ((lane >> 3) & 1) * 8) * 2);

#pragma unroll
    for (int ks = 0; ks < 8; ++ks) {
        const uint32_t kb = ks * 32;           // 16 halves = 32 bytes per kstep
        uint32_t ah[MF][4], al[MF][4];
#pragma unroll
        for (int mf = 0; mf < MF; ++mf) {
            const uint32_t mo = mf * (16 * SPITCH * 2);
            LDSM4(ah[mf], sAh + mo + aoff + kb);
            LDSM4(al[mf], sAl + mo + aoff + kb);
        }
        uint32_t bh[2][4], bl[2][4];
#pragma unroll
        for (int np = 0; np < 2; ++np) {
            const uint32_t no = np * (16 * SPITCH * 2);
            LDSM4(bh[np], sBh + no + boff + kb);
            LDSM4(bl[np], sBl + no + boff + kb);
        }
#pragma unroll
        for (int nf = 0; nf < 4; ++nf) {
            uint32_t bh0 = bh[nf >> 1][(nf & 1) * 2];
            uint32_t bh1 = bh[nf >> 1][(nf & 1) * 2 + 1];
            uint32_t bl0 = bl[nf >> 1][(nf & 1) * 2];
            uint32_t bl1 = bl[nf >> 1][(nf & 1) * 2 + 1];
#pragma unroll
            for (int mf = 0; mf < MF; ++mf) {
                MMA_BF16(acc[mf][nf], ah[mf], bh0, bh1);
                MMA_BF16(acc[mf][nf], ah[mf], bl0, bl1);
                MMA_BF16(acc[mf][nf], al[mf], bh0, bh1);
            }
        }
    }
}

// ---------------------------------------------------------------------------
// att GEMM (M=128, all 3 n-tiles, A resident) + in-smem softmax + prob store
// ---------------------------------------------------------------------------
__global__ void __launch_bounds__(256) att_kernel() {
    extern __shared__ __nv_bfloat16 sm[];
    __nv_bfloat16* Ah = sm;
    __nv_bfloat16* Al = sm + TILE_H;
    __nv_bfloat16* Bh = sm + 2 * TILE_H;
    __nv_bfloat16* Bl = sm + 3 * TILE_H;
    __half* att_s = (__half*)(sm + 4 * TILE_H);

    const int tid = threadIdx.x;
    const int bm = blockIdx.x * 128;
    const int wid = tid >> 5, lane = tid & 31;
    const int wm = wid >> 2, wn = wid & 3;
    const int g = lane >> 2, tg = lane & 3;

    load_tile<128>(g_xh, g_xl, Ah, Al, bm, NPIX, tid);

    for (int nt = 0; nt < 3; ++nt) {
        __syncthreads();
        load_tile<128>(g_wqkv_h, g_wqkv_l, Bh, Bl, nt * 128, NQKV, tid);
        __syncthreads();
        float acc[4][4][4];
        mma_compute<4>(Ah, Al, Bh, Bl, wm, wn, lane, acc);
#pragma unroll
        for (int mf = 0; mf < 4; ++mf) {
            int row = wm * 64 + mf * 16 + g;
#pragma unroll
            for (int nf = 0; nf < 4; ++nf) {
                int cc = nt * 128 + wn * 32 + nf * 8 + tg * 2;
                if (cc < NQKV) {
                    *(half2*)(att_s + row * APITCH + cc) =
                        __floats2half2_rn(acc[mf][nf][0], acc[mf][nf][1]);
                    *(half2*)(att_s + (row + 8) * APITCH + cc) =
                        __floats2half2_rn(acc[mf][nf][2], acc[mf][nf][3]);
                }
            }
        }
    }
    __syncthreads();

    // softmax over each 9-group, in smem
    const float scale = 0.17677669529663687f;  // 32^-0.5
    for (int t = tid; t < 128 * 36; t += 256) {
        int row = t / 36, grp = t % 36;
        __half* pp = att_s + row * APITCH + grp * 9;
        float v[9], m = -1e30f;
#pragma unroll
        for (int q = 0; q < 9; ++q) { v[q] = __half2float(pp[q]) * scale; m = fmaxf(m, v[q]); }
        float s = 0.f;
#pragma unroll
        for (int q = 0; q < 9; ++q) { v[q] = __expf(v[q] - m); s += v[q]; }
        float inv = 1.f / s;
#pragma unroll
        for (int q = 0; q < 9; ++q) pp[q] = __float2half_rn(v[q] * inv);
    }
    __syncthreads();

    // coalesced prob store
    for (int t = tid; t < 128 * NQKV; t += 256) {
        int row = t / NQKV, col = t - row * NQKV;
        g_attp[(size_t)(bm + row) * NQKV + col] = att_s[row * APITCH + col];
    }
}

// ---------------------------------------------------------------------------
// U GEMM: M=64 tiles (2 blocks/SM), A resident, loop 9 q-tiles
// ---------------------------------------------------------------------------
__global__ void __launch_bounds__(256) mma_u_kernel() {
    extern __shared__ __nv_bfloat16 sm[];
    __nv_bfloat16* Ah = sm;
    __nv_bfloat16* Al = sm + TILE64_H;
    __nv_bfloat16* Bh = sm + 2 * TILE64_H;
    __nv_bfloat16* Bl = sm + 2 * TILE64_H + TILE_H;

    const int tid = threadIdx.x;
    const int bm = blockIdx.x * 64;
    const int wid = tid >> 5, lane = tid & 31;
    const int wm = wid >> 2, wn = wid & 3;
    const int g = lane >> 2, tg = lane & 3;

    load_tile_async<64>(g_xh, g_xl, Ah, Al, bm, tid);
    CP_COMMIT();

    for (int q = 0; q < 9; ++q) {
        load_tile_async<128>(g_wv_h, g_wv_l, Bh, Bl, q * 128, tid);
        CP_COMMIT();
        CP_WAIT0();
        __syncthreads();

        float acc[2][4][4];
        mma_compute<2>(Ah, Al, Bh, Bl, wm, wn, lane, acc);

        __half* plane = g_u16 + (size_t)q * NPIX * CCH;
#pragma unroll
        for (int mf = 0; mf < 2; ++mf) {
            int row = bm + wm * 32 + mf * 16 + g;
#pragma unroll
            for (int nf = 0; nf < 4; ++nf) {
                int col = wn * 32 + nf * 8 + tg * 2;
                *(half2*)(plane + (size_t)row * 128 + col) =
                    __floats2half2_rn(acc[mf][nf][0], acc[mf][nf][1]);
                *(half2*)(plane + (size_t)(row + 8) * 128 + col) =
                    __floats2half2_rn(acc[mf][nf][2], acc[mf][nf][3]);
            }
        }
        __syncthreads();
    }
}

// ---------------------------------------------------------------------------
// projection GEMM: M=64 tiles (2 blocks/SM)
// ---------------------------------------------------------------------------
__global__ void __launch_bounds__(256) mma_proj_kernel(float* __restrict__ outp) {
    extern __shared__ __nv_bfloat16 sm[];
    __nv_bfloat16* Ah = sm;
    __nv_bfloat16* Al = sm + TILE64_H;
    __nv_bfloat16* Bh = sm + 2 * TILE64_H;
    __nv_bfloat16* Bl = sm + 2 * TILE64_H + TILE_H;

    const int tid = threadIdx.x;
    const int bm = blockIdx.x * 64;
    const int wid = tid >> 5, lane = tid & 31;
    const int wm = wid >> 2, wn = wid & 3;
    const int g = lane >> 2, tg = lane & 3;

    load_tile<64>(g_yh, g_yl, Ah, Al, bm, NPIX, tid);
    load_tile<128>(g_wpr_h, g_wpr_l, Bh, Bl, 0, CCH, tid);
    __syncthreads();
    float acc[2][4][4];
    mma_compute<2>(Ah, Al, Bh, Bl, wm, wn, lane, acc);
#pragma unroll
    for (int mf = 0; mf < 2; ++mf) {
        int row = bm + wm * 32 + mf * 16 + g;
#pragma unroll
        for (int nf = 0; nf < 4; ++nf) {
            int col = wn * 32 + nf * 8 + tg * 2;
            *(float2*)&outp[(size_t)row * 128 + col] =
                make_float2(acc[mf][nf][0], acc[mf][nf][1]);
            *(float2*)&outp[(size_t)(row + 8) * 128 + col] =
                make_float2(acc[mf][nf][2], acc[mf][nf][3]);
        }
    }
}

// ---------------------------------------------------------------------------
// combine: out[g][p][c] = sum_q att[g][h(c)][p][q] * U[g+off(q)][q][c]
// 4 pixels per block, 64 threads / pixel, half2 channels
// ---------------------------------------------------------------------------
__global__ void __launch_bounds__(256) combine_kernel() {
    const int sub = threadIdx.x >> 6;        // 0..3
    const int c2  = threadIdx.x & 63;        // half2 lane (channels 2*c2, 2*c2+1)
    const int g   = blockIdx.x * 4 + sub;
    __shared__ float att_s[4][NQKV];
    const __half* ap = g_attp + (size_t)g * NQKV;
    for (int t = c2; t < 162; t += 64) {
        float2 f = __half22float2(*(const half2*)(ap + t * 2));
        att_s[sub][t * 2] = f.x;
        att_s[sub][t * 2 + 1] = f.y;
    }
    __syncthreads();

    const int b = g >> 14;
    const int n = g & (HW - 1);
    const int i = n >> 7, j = n & 127;
    float2 v[9];
#pragma unroll
    for (int q = 0; q < 9; ++q) {
        int ii = i + q / 3 - 1;
        int jj = j + q % 3 - 1;
        bool valid = ((unsigned)ii < 128u) && ((unsigned)jj < 128u);
        v[q] = valid ? __half22float2(*(const half2*)&g_u16[
                   ((size_t)q * NPIX + ((b << 14) + (ii << 7) + jj)) * 128 + c2 * 2])
                     : make_float2(0.f, 0.f);
    }
    const float* ah = att_s[sub] + (c2 >> 4) * 81;
    float2 acc[9];
#pragma unroll
    for (int p2 = 0; p2 < 9; ++p2) acc[p2] = make_float2(0.f, 0.f);
#pragma unroll
    for (int q = 0; q < 9; ++q) {
        float2 vq = v[q];
#pragma unroll
        for (int p2 = 0; p2 < 9; ++p2) {
            float w = ah[p2 * 9 + q];
            acc[p2].x += w * vq.x;
            acc[p2].y += w * vq.y;
        }
    }
    __half* op = g_out16 + (size_t)g * NV + c2 * 2;
#pragma unroll
    for (int p2 = 0; p2 < 9; ++p2)
        *(half2*)(op + (p2 << 7)) = __floats2half2_rn(acc[p2].x, acc[p2].y);
}

// ---------------------------------------------------------------------------
// fold (gather), 4 channels/thread; writes bf16 hi/lo y
// ---------------------------------------------------------------------------
__global__ void fold_kernel() {
    int idx = blockIdx.x * blockDim.x + threadIdx.x;  // over NPIX*32
    if (idx >= NPIX * 32) return;
    int c4 = idx & 31;                 // channels 4*c4 .. 4*c4+3
    int g = idx >> 5;
    int b = g >> 14, n = g & (HW - 1);
    int i = n >> 7, j = n & 127;
    float a0 = 0.f, a1 = 0.f, a2 = 0.f, a3 = 0.f;
#pragma unroll
    for (int dr = -1; dr <= 1; ++dr) {
#pragma unroll
        for (int ds = -1; ds <= 1; ++ds) {
            int r = i + dr, s = j + ds;
            if ((unsigned)r < 128u && (unsigned)s < 128u) {
                int gp = (b << 14) + (r << 7) + s;
                int p2 = (1 - dr) * 3 + (1 - ds);
                const __half* src = &g_out16[(size_t)gp * NV + (p2 << 7) + c4 * 4];
                uint2 raw = *(const uint2*)src;
                float2 f0 = __half22float2(*(half2*)&raw.x);
                float2 f1 = __half22float2(*(half2*)&raw.y);
                a0 += f0.x; a1 += f0.y; a2 += f1.x; a3 += f1.y;
            }
        }
    }
    __nv_bfloat16 h0, l0, h1, l1, h2, l2, h3, l3;
    split_bf16(a0, h0, l0);
    split_bf16(a1, h1, l1);
    split_bf16(a2, h2, l2);
    split_bf16(a3, h3, l3);
    size_t o = (size_t)g * 128 + c4 * 4;
    __nv_bfloat162 hh0(h0, h1), hh1(h2, h3), ll0(l0, l1), ll1(l2, l3);
    *(uint2*)&g_yh[o] = make_uint2(*(uint32_t*)&hh0, *(uint32_t*)&hh1);
    *(uint2*)&g_yl[o] = make_uint2(*(uint32_t*)&ll0, *(uint32_t*)&ll1);
}

// ---------------------------------------------------------------------------
extern "C" void kernel_launch(void* const* d_in, const int* in_sizes, int n_in,
                              void* d_out, int out_size) {
    const float* x     = (const float*)d_in[0];
    const float* wqkv  = (const float*)d_in[1];
    const float* wv    = (const float*)d_in[2];
    const float* wproj = (const float*)d_in[3];
    float* out = (float*)d_out;

    cudaFuncSetAttribute(att_kernel,      cudaFuncAttributeMaxDynamicSharedMemorySize, ATT_SMEM);
    cudaFuncSetAttribute(mma_u_kernel,    cudaFuncAttributeMaxDynamicSharedMemorySize, G64_SMEM);
    cudaFuncSetAttribute(mma_proj_kernel, cudaFuncAttributeMaxDynamicSharedMemorySize, G64_SMEM);

    conv_x_kernel<<<(NPIX * 64 + 255) / 256, 256>>>(x);
    conv_w_kernel<<<(NV * CCH + 255) / 256, 256>>>(wqkv, wv, wproj);

    att_kernel<<<512, 256, ATT_SMEM>>>();
    mma_u_kernel<<<1024, 256, G64_SMEM>>>();
    combine_kernel<<<NPIX / 4, 256>>>();
    fold_kernel<<<(NPIX * 32 + 255) / 256, 256>>>();
    mma_proj_kernel<<<1024, 256, G64_SMEM>>>(out);
}